// round 13
// baseline (speedup 1.0000x reference)
#include <cuda_runtime.h>
#include <cuda_fp16.h>
#include <math.h>
#include <stdint.h>

#define Bq 256
#define Sq 10
#define Hq 1024
#define Vq 32000
#define Tq 10
#define BT (Bq * Tq)

// ---------------- device scratch (no allocation) ----------------
__device__ __align__(16) float g_keysA[(size_t)Bq * Sq * 4096];  // [ keysW(1024) | keysC(3072) ]
__device__ int   g_tokens[Bq * Tq];
__device__ __align__(16) float g_qgh[Bq * 4096];
__device__ __align__(16) float g_gie[(size_t)BT * 3 * Hq];
__device__ __align__(16) float g_h0[Bq * Hq];
__device__ __align__(16) float g_h1[Bq * Hq];
__device__ __align__(16) float g_logits_all[(size_t)BT * Vq];
__device__ __align__(16) float g_bcat[4096];
__device__ __align__(16) float g_bkA[4096];

__device__ __align__(16) __half g_enc_h[(size_t)Bq * Sq * Hq];
__device__ __align__(16) __half g_e_h[(size_t)BT * Hq];
__device__ __align__(16) __half g_WkA[(size_t)4096 * Hq];   // [Wa; Wc]
__device__ __align__(16) __half g_Wqh[(size_t)4096 * Hq];   // [Ua; Whh]
__device__ __align__(16) __half g_We[(size_t)3 * Hq * Hq];
__device__ __align__(16) __half g_h_h[Bq * Hq];

// int8 path for logits
__device__ __align__(16) int8_t g_hq[(size_t)BT * Hq];
__device__ __align__(16) float  g_sH[BT];
__device__ __align__(16) int8_t g_Wq[(size_t)Vq * Hq];
__device__ __align__(16) float  g_sW[Vq];

// ---------------- fp16 HMMA GEMM: 3-stage cp.async ring ----------------
template <int BM, int BN, int BK, int WM, int WN, int MINB>
__global__ void __launch_bounds__((BM / WM) * (BN / WN) * 32, MINB)
gemm_fp16_bias(const __half* __restrict__ A, const __half* __restrict__ B,
               const float* __restrict__ bias, float* __restrict__ C,
               int M, int N, int K)
{
    constexpr int WARPS_M = BM / WM;
    constexpr int WARPS_N = BN / WN;
    constexpr int THREADS = WARPS_M * WARPS_N * 32;
    constexpr int PAD = 8;
    constexpr int LDS_ = BK + PAD;
    constexpr int MI = WM / 16;
    constexpr int NI = WN / 8;

    extern __shared__ char smem_raw[];
    __half* As = (__half*)smem_raw;
    __half* Bs = (__half*)(smem_raw + 3 * BM * LDS_ * 2);

    const int tid = threadIdx.x;
    const int wid = tid / 32, lane = tid % 32;
    const int wm = (wid / WARPS_N) * WM;
    const int wn = (wid % WARPS_N) * WN;
    const int bm = blockIdx.y * BM;
    const int bn = blockIdx.x * BN;

    constexpr int A_CH = BM * BK / 8;
    constexpr int B_CH = BN * BK / 8;
    constexpr int CPR = BK / 8;

    const int NK = K / BK;

    auto load_stage = [&](int stage) {
        __half* Asd = As + (stage % 3) * BM * LDS_;
        __half* Bsd = Bs + (stage % 3) * BN * LDS_;
        const int k0 = stage * BK;
#pragma unroll
        for (int c = tid; c < A_CH; c += THREADS) {
            int r = c / CPR, cc = (c % CPR) * 8;
            uint32_t sdst = (uint32_t)__cvta_generic_to_shared(&Asd[r * LDS_ + cc]);
            const __half* src = &A[(size_t)(bm + r) * K + k0 + cc];
            asm volatile("cp.async.cg.shared.global [%0], [%1], 16;" :: "r"(sdst), "l"(src));
        }
#pragma unroll
        for (int c = tid; c < B_CH; c += THREADS) {
            int r = c / CPR, cc = (c % CPR) * 8;
            uint32_t sdst = (uint32_t)__cvta_generic_to_shared(&Bsd[r * LDS_ + cc]);
            const __half* src = &B[(size_t)(bn + r) * K + k0 + cc];
            asm volatile("cp.async.cg.shared.global [%0], [%1], 16;" :: "r"(sdst), "l"(src));
        }
        asm volatile("cp.async.commit_group;");
    };

    float acc[MI][NI][4];
#pragma unroll
    for (int i = 0; i < MI; i++)
#pragma unroll
        for (int j = 0; j < NI; j++)
#pragma unroll
            for (int k = 0; k < 4; k++) acc[i][j][k] = 0.f;

    load_stage(0);
    if (NK > 1) load_stage(1);

    const int a_row = lane % 16;
    const int a_col = (lane / 16) * 8;
    const int b_t   = lane & 15;
    const int b_row = b_t % 8;
    const int b_col = (b_t / 8) * 8;

    for (int kt = 0; kt < NK; kt++) {
        if (kt + 1 < NK) {
            asm volatile("cp.async.wait_group 1;");
        } else {
            asm volatile("cp.async.wait_group 0;");
        }
        __syncthreads();

        if (kt + 2 < NK) load_stage(kt + 2);

        __half* Asb = As + (kt % 3) * BM * LDS_;
        __half* Bsb = Bs + (kt % 3) * BN * LDS_;

#pragma unroll
        for (int kk = 0; kk < BK; kk += 16) {
            uint32_t af[MI][4];
#pragma unroll
            for (int mi = 0; mi < MI; mi++) {
                uint32_t addr = (uint32_t)__cvta_generic_to_shared(
                    &Asb[(wm + mi * 16 + a_row) * LDS_ + kk + a_col]);
                asm volatile("ldmatrix.sync.aligned.m8n8.x4.shared.b16 {%0,%1,%2,%3}, [%4];"
                             : "=r"(af[mi][0]), "=r"(af[mi][1]), "=r"(af[mi][2]), "=r"(af[mi][3])
                             : "r"(addr));
            }
            uint32_t bf[NI][2];
#pragma unroll
            for (int ni = 0; ni < NI; ni++) {
                uint32_t addr = (uint32_t)__cvta_generic_to_shared(
                    &Bsb[(wn + ni * 8 + b_row) * LDS_ + kk + b_col]);
                asm volatile("ldmatrix.sync.aligned.m8n8.x2.shared.b16 {%0,%1}, [%2];"
                             : "=r"(bf[ni][0]), "=r"(bf[ni][1])
                             : "r"(addr));
            }
#pragma unroll
            for (int mi = 0; mi < MI; mi++) {
#pragma unroll
                for (int ni = 0; ni < NI; ni++) {
                    asm volatile(
                        "mma.sync.aligned.m16n8k16.row.col.f32.f16.f16.f32 "
                        "{%0,%1,%2,%3}, {%4,%5,%6,%7}, {%8,%9}, {%0,%1,%2,%3};"
                        : "+f"(acc[mi][ni][0]), "+f"(acc[mi][ni][1]),
                          "+f"(acc[mi][ni][2]), "+f"(acc[mi][ni][3])
                        : "r"(af[mi][0]), "r"(af[mi][1]), "r"(af[mi][2]), "r"(af[mi][3]),
                          "r"(bf[ni][0]), "r"(bf[ni][1]));
                }
            }
        }
    }

#pragma unroll
    for (int mi = 0; mi < MI; mi++) {
        int row0 = bm + wm + mi * 16 + lane / 4;
#pragma unroll
        for (int ni = 0; ni < NI; ni++) {
            int col = bn + wn + ni * 8 + 2 * (lane % 4);
            float2 bv = *(const float2*)&bias[col];
            float2 v0 = make_float2(acc[mi][ni][0] + bv.x, acc[mi][ni][1] + bv.y);
            float2 v1 = make_float2(acc[mi][ni][2] + bv.x, acc[mi][ni][3] + bv.y);
            *(float2*)&C[(size_t)row0 * N + col] = v0;
            *(float2*)&C[(size_t)(row0 + 8) * N + col] = v1;
        }
    }
}

// ---------------- int8 IMMA GEMM (m16n8k32.s8): C = (A q) (B q)^T * sa*sb + bias ----------------
// BM=128, BN=128, BK=128 s8 elems, WM=64, WN=32, 256 threads.
__global__ void __launch_bounds__(256, 2)
gemm_s8_scaled(const int8_t* __restrict__ A, const int8_t* __restrict__ B,
               const float* __restrict__ saA, const float* __restrict__ sbB,
               const float* __restrict__ bias, float* __restrict__ C,
               int M, int N, int K)
{
    constexpr int BM = 128, BN = 128, BK = 128;
    constexpr int WM = 64, WN = 32;
    constexpr int THREADS = 256;
    constexpr int PAD = 16;
    constexpr int LDS_ = BK + PAD;  // bytes per row
    constexpr int MI = WM / 16;     // 4
    constexpr int NI = WN / 8;      // 4
    constexpr int WARPS_N = BN / WN;

    extern __shared__ char smem_raw[];
    int8_t* As = (int8_t*)smem_raw;                       // [3][BM*LDS_]
    int8_t* Bs = (int8_t*)(smem_raw + 3 * BM * LDS_);

    const int tid = threadIdx.x;
    const int wid = tid / 32, lane = tid % 32;
    const int wm = (wid / WARPS_N) * WM;
    const int wn = (wid % WARPS_N) * WN;
    const int bm = blockIdx.y * BM;
    const int bn = blockIdx.x * BN;

    constexpr int CPR = BK / 16;        // 16B chunks per row = 8
    constexpr int A_CH = BM * CPR;      // 1024
    constexpr int B_CH = BN * CPR;

    const int NK = K / BK;              // 8

    auto load_stage = [&](int stage) {
        int8_t* Asd = As + (stage % 3) * BM * LDS_;
        int8_t* Bsd = Bs + (stage % 3) * BN * LDS_;
        const int k0 = stage * BK;
#pragma unroll
        for (int c = tid; c < A_CH; c += THREADS) {
            int r = c / CPR, cc = (c % CPR) * 16;
            uint32_t sdst = (uint32_t)__cvta_generic_to_shared(&Asd[r * LDS_ + cc]);
            const int8_t* src = &A[(size_t)(bm + r) * K + k0 + cc];
            asm volatile("cp.async.cg.shared.global [%0], [%1], 16;" :: "r"(sdst), "l"(src));
        }
#pragma unroll
        for (int c = tid; c < B_CH; c += THREADS) {
            int r = c / CPR, cc = (c % CPR) * 16;
            uint32_t sdst = (uint32_t)__cvta_generic_to_shared(&Bsd[r * LDS_ + cc]);
            const int8_t* src = &B[(size_t)(bn + r) * K + k0 + cc];
            asm volatile("cp.async.cg.shared.global [%0], [%1], 16;" :: "r"(sdst), "l"(src));
        }
        asm volatile("cp.async.commit_group;");
    };

    int acc[MI][NI][4];
#pragma unroll
    for (int i = 0; i < MI; i++)
#pragma unroll
        for (int j = 0; j < NI; j++)
#pragma unroll
            for (int k = 0; k < 4; k++) acc[i][j][k] = 0;

    load_stage(0);
    if (NK > 1) load_stage(1);

    const int a_row = lane % 16;
    const int a_sel = (lane / 16) * 16;   // byte offset within 32B k-slice
    const int b_t   = lane & 15;
    const int b_row = b_t % 8;
    const int b_sel = (b_t / 8) * 16;

    for (int kt = 0; kt < NK; kt++) {
        if (kt + 1 < NK) {
            asm volatile("cp.async.wait_group 1;");
        } else {
            asm volatile("cp.async.wait_group 0;");
        }
        __syncthreads();

        if (kt + 2 < NK) load_stage(kt + 2);

        int8_t* Asb = As + (kt % 3) * BM * LDS_;
        int8_t* Bsb = Bs + (kt % 3) * BN * LDS_;

#pragma unroll
        for (int kk = 0; kk < BK; kk += 32) {   // k32 per mma
            uint32_t af[MI][4];
#pragma unroll
            for (int mi = 0; mi < MI; mi++) {
                uint32_t addr = (uint32_t)__cvta_generic_to_shared(
                    &Asb[(wm + mi * 16 + a_row) * LDS_ + kk + a_sel]);
                asm volatile("ldmatrix.sync.aligned.m8n8.x4.shared.b16 {%0,%1,%2,%3}, [%4];"
                             : "=r"(af[mi][0]), "=r"(af[mi][1]), "=r"(af[mi][2]), "=r"(af[mi][3])
                             : "r"(addr));
            }
            uint32_t bf[NI][2];
#pragma unroll
            for (int ni = 0; ni < NI; ni++) {
                uint32_t addr = (uint32_t)__cvta_generic_to_shared(
                    &Bsb[(wn + ni * 8 + b_row) * LDS_ + kk + b_sel]);
                asm volatile("ldmatrix.sync.aligned.m8n8.x2.shared.b16 {%0,%1}, [%2];"
                             : "=r"(bf[ni][0]), "=r"(bf[ni][1])
                             : "r"(addr));
            }
#pragma unroll
            for (int mi = 0; mi < MI; mi++) {
#pragma unroll
                for (int ni = 0; ni < NI; ni++) {
                    asm volatile(
                        "mma.sync.aligned.m16n8k32.row.col.s32.s8.s8.s32 "
                        "{%0,%1,%2,%3}, {%4,%5,%6,%7}, {%8,%9}, {%0,%1,%2,%3};"
                        : "+r"(acc[mi][ni][0]), "+r"(acc[mi][ni][1]),
                          "+r"(acc[mi][ni][2]), "+r"(acc[mi][ni][3])
                        : "r"(af[mi][0]), "r"(af[mi][1]), "r"(af[mi][2]), "r"(af[mi][3]),
                          "r"(bf[ni][0]), "r"(bf[ni][1]));
                }
            }
        }
    }

#pragma unroll
    for (int mi = 0; mi < MI; mi++) {
        int row0 = bm + wm + mi * 16 + lane / 4;
        float sA0 = saA[row0], sA1 = saA[row0 + 8];
#pragma unroll
        for (int ni = 0; ni < NI; ni++) {
            int col = bn + wn + ni * 8 + 2 * (lane % 4);
            float2 bv = *(const float2*)&bias[col];
            float sB0 = sbB[col], sB1 = sbB[col + 1];
            float2 v0 = make_float2((float)acc[mi][ni][0] * sA0 * sB0 + bv.x,
                                    (float)acc[mi][ni][1] * sA0 * sB1 + bv.y);
            float2 v1 = make_float2((float)acc[mi][ni][2] * sA1 * sB0 + bv.x,
                                    (float)acc[mi][ni][3] * sA1 * sB1 + bv.y);
            *(float2*)&C[(size_t)row0 * N + col] = v0;
            *(float2*)&C[(size_t)(row0 + 8) * N + col] = v1;
        }
    }
}

// smem sizes
#define DSM_BIG   (3 * (128 + 128) * (64 + 8) * 2)   // 110592 fp16 big tile
#define DSM_SMALL (3 * (64 + 64) * (64 + 8) * 2)     // 55296
#define DSM_S8    (3 * (128 + 128) * (128 + 16))     // 110592 s8 tile

#define GEMM_BIG   gemm_fp16_bias<128, 128, 64, 64, 32, 2>
#define GEMM_SMALL gemm_fp16_bias<64, 64, 64, 32, 32, 4>

// ---------------- setup / conversion kernels ----------------
__global__ void init_tokens_kernel(const int* __restrict__ target)
{
    int b = threadIdx.x;
    g_tokens[b * Tq + 0] = 0;  // SOS
    for (int t = 1; t < Tq; t++) g_tokens[b * Tq + t] = target[b * Tq + t - 1];
}

__global__ void f2h_kernel(const float* __restrict__ src, __half* __restrict__ dst, int n4)
{
    int i = blockIdx.x * blockDim.x + threadIdx.x;
    if (i >= n4) return;
    float4 v = ((const float4*)src)[i];
    __half2 lo = __floats2half2_rn(v.x, v.y);
    __half2 hi = __floats2half2_rn(v.z, v.w);
    uint2 o;
    o.x = *(uint32_t*)&lo;
    o.y = *(uint32_t*)&hi;
    ((uint2*)dst)[i] = o;
}

__global__ void slice_h_kernel(const float* __restrict__ src, __half* __restrict__ dst,
                               int N, int K, int stride, int off)
{
    int i = blockIdx.x * blockDim.x + threadIdx.x;
    if (i >= N * K) return;
    int n = i / K, k = i % K;
    dst[i] = __float2half_rn(src[(size_t)n * stride + off + k]);
}

__global__ void emb_h_kernel(const float* __restrict__ emb)
{
    int i = blockIdx.x * blockDim.x + threadIdx.x;
    int r = i / Hq, j = i % Hq;
    int t = r / Bq, b = r % Bq;
    g_e_h[i] = __float2half_rn(emb[(size_t)g_tokens[b * Tq + t] * Hq + j]);
}

__global__ void bias_cat_kernel(const float* __restrict__ bua, const float* __restrict__ bhh,
                                const float* __restrict__ ba)
{
    int i = blockIdx.x * blockDim.x + threadIdx.x;  // 4096
    g_bcat[i] = (i < Hq) ? bua[i] : bhh[i - Hq];
    g_bkA[i]  = (i < Hq) ? ba[i] : 0.f;
}

__global__ void copy_h0_kernel(float* __restrict__ dst, const float* __restrict__ src)
{
    int i = blockIdx.x * blockDim.x + threadIdx.x;
    float v = src[i];
    dst[i] = v;
    g_h_h[i] = __float2half_rn(v);
}

__global__ void copy_kernel(float* __restrict__ dst, const float* __restrict__ src)
{
    int i = blockIdx.x * blockDim.x + threadIdx.x;
    dst[i] = src[i];
}

// per-row symmetric int8 quant: one block per row (128 threads)
__global__ void __launch_bounds__(128)
quant_rows_kernel(const float* __restrict__ src, int8_t* __restrict__ dst,
                  float* __restrict__ scales, int K)
{
    int r = blockIdx.x, tid = threadIdx.x;
    const float* row = src + (size_t)r * K;
    float mx = 0.f;
    for (int j = tid; j < K; j += 128) mx = fmaxf(mx, fabsf(row[j]));
    __shared__ float smx[4];
    int lane = tid & 31, warp = tid >> 5;
#pragma unroll
    for (int o = 16; o > 0; o >>= 1) mx = fmaxf(mx, __shfl_xor_sync(0xffffffffu, mx, o));
    if (lane == 0) smx[warp] = mx;
    __syncthreads();
    float m = fmaxf(fmaxf(smx[0], smx[1]), fmaxf(smx[2], smx[3]));
    m = fmaxf(m, 1e-12f);
    float sc = m / 127.f, inv = 127.f / m;
    if (tid == 0) scales[r] = sc;
    for (int j = tid; j < K; j += 128) {
        float q = rintf(row[j] * inv);
        dst[(size_t)r * K + j] = (int8_t)max(-127.f, min(127.f, q));
    }
}

// ---------------- fused attention + GRU (+ int8 quant of h row) ----------------
__global__ void __launch_bounds__(128)
attn_gru_kernel(const float* __restrict__ Va, const float* __restrict__ bva,
                float* __restrict__ att_out,
                const float* __restrict__ hcur, float* __restrict__ hnext, int t)
{
    const int b = blockIdx.x;
    const int tid = threadIdx.x;

    float partial[Sq];
#pragma unroll
    for (int s = 0; s < Sq; s++) partial[s] = 0.f;

    for (int h = tid; h < Hq; h += 128) {
        float qv = g_qgh[b * 4096 + h];
        float va = Va[h];
#pragma unroll
        for (int s = 0; s < Sq; s++) {
            float kw = g_keysA[((size_t)b * Sq + s) * 4096 + h];
            partial[s] += va * tanhf(kw + qv);
        }
    }

    __shared__ float red[4][Sq];
    __shared__ float w[Sq];
    __shared__ float gic_s[3 * Hq];
    __shared__ float hv_s[Hq];
    __shared__ float hmax_sh[4];
    int lane = tid & 31, warp = tid >> 5;
#pragma unroll
    for (int s = 0; s < Sq; s++) {
        float v = partial[s];
#pragma unroll
        for (int o = 16; o > 0; o >>= 1) v += __shfl_xor_sync(0xffffffffu, v, o);
        if (lane == 0) red[warp][s] = v;
    }
    __syncthreads();

    if (tid == 0) {
        float scv[Sq], mx = -1e30f;
#pragma unroll
        for (int s = 0; s < Sq; s++) {
            scv[s] = red[0][s] + red[1][s] + red[2][s] + red[3][s] + bva[0];
            mx = fmaxf(mx, scv[s]);
        }
        float sum = 0.f;
#pragma unroll
        for (int s = 0; s < Sq; s++) { scv[s] = expf(scv[s] - mx); sum += scv[s]; }
        float inv = 1.f / sum;
#pragma unroll
        for (int s = 0; s < Sq; s++) w[s] = scv[s] * inv;
    }
    __syncthreads();

    if (tid < Sq) att_out[(size_t)b * (Tq * Sq) + t * Sq + tid] = w[tid];

    const float* kA = g_keysA + (size_t)b * Sq * 4096 + 1024;
    for (int j = tid; j < 3 * Hq; j += 128) {
        float acc = 0.f;
#pragma unroll
        for (int s = 0; s < Sq; s++)
            acc += w[s] * kA[(size_t)s * 4096 + j];
        gic_s[j] = acc;
    }
    __syncthreads();

    // GRU pointwise for row b; also track absmax for int8 quant
    const float* gie = g_gie + (size_t)(t * Bq + b) * 3 * Hq;
    const float* gh  = g_qgh + (size_t)b * 4096 + Hq;
    float hmax = 0.f;
    for (int j = tid; j < Hq; j += 128) {
        float r = 1.f / (1.f + expf(-(gie[j] + gic_s[j] + gh[j])));
        float z = 1.f / (1.f + expf(-(gie[Hq + j] + gic_s[Hq + j] + gh[Hq + j])));
        float n = tanhf(gie[2 * Hq + j] + gic_s[2 * Hq + j] + r * gh[2 * Hq + j]);
        float hv = (1.f - z) * n + z * hcur[b * Hq + j];
        hnext[b * Hq + j] = hv;
        hv_s[j] = hv;
        hmax = fmaxf(hmax, fabsf(hv));
        g_h_h[b * Hq + j] = __float2half_rn(hv);
    }
#pragma unroll
    for (int o = 16; o > 0; o >>= 1) hmax = fmaxf(hmax, __shfl_xor_sync(0xffffffffu, hmax, o));
    if (lane == 0) hmax_sh[warp] = hmax;
    __syncthreads();
    float m = fmaxf(fmaxf(hmax_sh[0], hmax_sh[1]), fmaxf(hmax_sh[2], hmax_sh[3]));
    m = fmaxf(m, 1e-12f);
    float sc = m / 127.f, inv = 127.f / m;
    if (tid == 0) g_sH[t * Bq + b] = sc;
    int8_t* hq = g_hq + (size_t)(t * Bq + b) * Hq;
    for (int j = tid; j < Hq; j += 128) {
        float q = rintf(hv_s[j] * inv);
        hq[j] = (int8_t)max(-127.f, min(127.f, q));
    }
}

// ---------------- batched log_softmax (row r = t*Bq + b -> out[b][t]) ----------------
__global__ void __launch_bounds__(256)
logsoftmax_all_kernel(float* __restrict__ out)
{
    const int r = blockIdx.x, tid = threadIdx.x;
    const int t = r / Bq, b = r % Bq;
    const float* row = g_logits_all + (size_t)r * Vq;

    float m = -1e30f, s = 0.f;
    for (int v = tid; v < Vq; v += 256) {
        float x = row[v];
        float nm = fmaxf(m, x);
        s = s * expf(m - nm) + expf(x - nm);
        m = nm;
    }
    int lane = tid & 31, warp = tid >> 5;
#pragma unroll
    for (int o = 16; o > 0; o >>= 1) {
        float m2 = __shfl_xor_sync(0xffffffffu, m, o);
        float s2 = __shfl_xor_sync(0xffffffffu, s, o);
        float nm = fmaxf(m, m2);
        s = s * expf(m - nm) + s2 * expf(m2 - nm);
        m = nm;
    }
    __shared__ float sm[8], ss[8];
    __shared__ float lse_sh;
    if (lane == 0) { sm[warp] = m; ss[warp] = s; }
    __syncthreads();
    if (tid == 0) {
        float M = sm[0], S = ss[0];
#pragma unroll
        for (int i = 1; i < 8; i++) {
            float nm = fmaxf(M, sm[i]);
            S = S * expf(M - nm) + ss[i] * expf(sm[i] - nm);
            M = nm;
        }
        lse_sh = M + logf(S);
    }
    __syncthreads();
    float lse = lse_sh;
    float* orow = out + ((size_t)b * Tq + t) * Vq;
    for (int v = tid; v < Vq; v += 256) orow[v] = row[v] - lse;
}

// ---------------- launch ----------------
extern "C" void kernel_launch(void* const* d_in, const int* in_sizes, int n_in,
                              void* d_out, int out_size)
{
    const float* enc_out = (const float*)d_in[0];
    const float* enc_hid = (const float*)d_in[1];
    const int*   target  = (const int*)  d_in[2];
    const float* emb     = (const float*)d_in[3];
    const float* Wa      = (const float*)d_in[4];
    const float* ba      = (const float*)d_in[5];
    const float* Ua      = (const float*)d_in[6];
    const float* bua     = (const float*)d_in[7];
    const float* Va      = (const float*)d_in[8];
    const float* bva     = (const float*)d_in[9];
    const float* W_ih    = (const float*)d_in[10];
    const float* W_hh    = (const float*)d_in[11];
    const float* b_ih    = (const float*)d_in[12];
    const float* b_hh    = (const float*)d_in[13];
    const float* W_out   = (const float*)d_in[14];
    const float* b_out   = (const float*)d_in[15];

    float* out = (float*)d_out;
    const size_t HID_OFF = (size_t)Bq * Tq * Vq;
    const size_t ATT_OFF = HID_OFF + (size_t)Bq * Hq;

    float *keysA, *gie, *h0, *h1, *logitsA, *bcat, *bkA, *qgh, *sH, *sW;
    __half *enc_h, *e_h, *WkA, *Wqh, *We, *h_h;
    int8_t *hq, *Wq;
    cudaGetSymbolAddress((void**)&keysA, g_keysA);
    cudaGetSymbolAddress((void**)&gie, g_gie);
    cudaGetSymbolAddress((void**)&h0, g_h0);
    cudaGetSymbolAddress((void**)&h1, g_h1);
    cudaGetSymbolAddress((void**)&logitsA, g_logits_all);
    cudaGetSymbolAddress((void**)&bcat, g_bcat);
    cudaGetSymbolAddress((void**)&bkA, g_bkA);
    cudaGetSymbolAddress((void**)&qgh, g_qgh);
    cudaGetSymbolAddress((void**)&enc_h, g_enc_h);
    cudaGetSymbolAddress((void**)&e_h, g_e_h);
    cudaGetSymbolAddress((void**)&WkA, g_WkA);
    cudaGetSymbolAddress((void**)&Wqh, g_Wqh);
    cudaGetSymbolAddress((void**)&We, g_We);
    cudaGetSymbolAddress((void**)&h_h, g_h_h);
    cudaGetSymbolAddress((void**)&hq, g_hq);
    cudaGetSymbolAddress((void**)&sH, g_sH);
    cudaGetSymbolAddress((void**)&Wq, g_Wq);
    cudaGetSymbolAddress((void**)&sW, g_sW);

    cudaFuncSetAttribute((const void*)GEMM_BIG,
                         cudaFuncAttributeMaxDynamicSharedMemorySize, DSM_BIG);
    cudaFuncSetAttribute((const void*)GEMM_SMALL,
                         cudaFuncAttributeMaxDynamicSharedMemorySize, DSM_SMALL);
    cudaFuncSetAttribute((const void*)gemm_s8_scaled,
                         cudaFuncAttributeMaxDynamicSharedMemorySize, DSM_S8);

    // ---- setup ----
    init_tokens_kernel<<<1, 256>>>(target);                                             // 1
    emb_h_kernel<<<(BT * Hq) / 256, 256>>>(emb);                                        // 2
    slice_h_kernel<<<(3 * Hq * Hq + 255) / 256, 256>>>(W_ih, We, 3 * Hq, Hq, 2 * Hq, 0);// 3
    // gi_e all steps = E @ W_e^T + b_ih  (M=2560, N=3072, K=1024)                      // 4
    GEMM_BIG<<<dim3(3 * Hq / 128, BT / 128), 256, DSM_BIG>>>(
        e_h, We, b_ih, gie, BT, 3 * Hq, Hq);

    f2h_kernel<<<(Bq * Sq * Hq / 4 + 255) / 256, 256>>>(enc_out, enc_h, Bq * Sq * Hq / 4);
    f2h_kernel<<<(Hq * Hq / 4 + 255) / 256, 256>>>(Wa, WkA, Hq * Hq / 4);
    slice_h_kernel<<<(3 * Hq * Hq + 255) / 256, 256>>>(W_ih, WkA + (size_t)Hq * Hq,
                                                       3 * Hq, Hq, 2 * Hq, Hq);
    bias_cat_kernel<<<16, 256>>>(bua, b_hh, ba);
    // keysA = enc @ [Wa;Wc]^T + [ba|0]  (M=2560, N=4096, K=1024)
    GEMM_BIG<<<dim3(4096 / 128, (Bq * Sq) / 128), 256, DSM_BIG>>>(
        enc_h, WkA, bkA, keysA, Bq * Sq, 4096, Hq);

    copy_h0_kernel<<<(Bq * Hq) / 256, 256>>>(h0, enc_hid);
    quant_rows_kernel<<<Vq, 128>>>(W_out, Wq, sW, Hq);   // W_out -> int8 per-row
    f2h_kernel<<<(Hq * Hq / 4 + 255) / 256, 256>>>(Ua, Wqh, Hq * Hq / 4);
    f2h_kernel<<<(3 * Hq * Hq / 4 + 255) / 256, 256>>>(W_hh, Wqh + (size_t)Hq * Hq,
                                                       3 * Hq * Hq / 4);

    float* hcur = h0;
    float* hnext = h1;
    for (int t = 0; t < Tq; t++) {
        // [q | gh] = h @ [Ua; W_hh]^T + [bua | b_hh]  (M=256, N=4096, K=1024)
        GEMM_SMALL<<<dim3(4096 / 64, Bq / 64), 128, DSM_SMALL>>>(
            h_h, Wqh, bcat, qgh, Bq, 4096, Hq);
        attn_gru_kernel<<<Bq, 128>>>(Va, bva, out + ATT_OFF, hcur, hnext, t);
        float* tmp = hcur; hcur = hnext; hnext = tmp;
    }

    // logits for all steps = dequant( hq @ Wq^T ) + b_out  (int8 IMMA, M=2560, N=32000, K=1024)
    gemm_s8_scaled<<<dim3(Vq / 128, BT / 128), 256, DSM_S8>>>(
        hq, Wq, sH, sW, b_out, logitsA, BT, Vq, Hq);
    logsoftmax_all_kernel<<<BT, 256>>>(out);

    copy_kernel<<<(Bq * Hq) / 256, 256>>>(out + HID_OFF, hcur);
}

// round 14
// speedup vs baseline: 1.2218x; 1.2218x over previous
#include <cuda_runtime.h>
#include <cuda_fp16.h>
#include <math.h>
#include <stdint.h>

#define Bq 256
#define Sq 10
#define Hq 1024
#define Vq 32000
#define Tq 10
#define BT (Bq * Tq)

// ---------------- device scratch (no allocation) ----------------
__device__ __align__(16) float g_keysA[(size_t)Bq * Sq * 4096];  // [ keysW(1024) | keysC(3072) ]
__device__ int   g_tokens[Bq * Tq];
__device__ __align__(16) float g_qgh[Bq * 4096];
__device__ __align__(16) float g_gie[(size_t)BT * 3 * Hq];
__device__ __align__(16) float g_h0[Bq * Hq];
__device__ __align__(16) float g_h1[Bq * Hq];
__device__ __align__(16) float g_logits_all[(size_t)BT * Vq];
__device__ __align__(16) float g_bcat[4096];
__device__ __align__(16) float g_bkA[4096];

__device__ __align__(16) __half g_enc_h[(size_t)Bq * Sq * Hq];
__device__ __align__(16) __half g_e_h[(size_t)BT * Hq];
__device__ __align__(16) __half g_WkA[(size_t)4096 * Hq];   // [Wa; Wc]
__device__ __align__(16) __half g_Wqh[(size_t)4096 * Hq];   // [Ua; Whh]
__device__ __align__(16) __half g_We[(size_t)3 * Hq * Hq];
__device__ __align__(16) __half g_h_h[Bq * Hq];
__device__ __align__(16) __half g_hall[(size_t)BT * Hq];
__device__ __align__(16) __half g_Wout_h[(size_t)Vq * Hq];

// ---------------- fp16 HMMA GEMM: 3-stage cp.async ring ----------------
template <int BM, int BN, int BK, int WM, int WN, int MINB>
__global__ void __launch_bounds__((BM / WM) * (BN / WN) * 32, MINB)
gemm_fp16_bias(const __half* __restrict__ A, const __half* __restrict__ B,
               const float* __restrict__ bias, float* __restrict__ C,
               int M, int N, int K)
{
    constexpr int WARPS_M = BM / WM;
    constexpr int WARPS_N = BN / WN;
    constexpr int THREADS = WARPS_M * WARPS_N * 32;
    constexpr int PAD = 8;
    constexpr int LDS_ = BK + PAD;
    constexpr int MI = WM / 16;
    constexpr int NI = WN / 8;

    extern __shared__ char smem_raw[];
    __half* As = (__half*)smem_raw;
    __half* Bs = (__half*)(smem_raw + 3 * BM * LDS_ * 2);

    const int tid = threadIdx.x;
    const int wid = tid / 32, lane = tid % 32;
    const int wm = (wid / WARPS_N) * WM;
    const int wn = (wid % WARPS_N) * WN;
    const int bm = blockIdx.y * BM;
    const int bn = blockIdx.x * BN;

    constexpr int A_CH = BM * BK / 8;
    constexpr int B_CH = BN * BK / 8;
    constexpr int CPR = BK / 8;

    const int NK = K / BK;

    auto load_stage = [&](int stage) {
        __half* Asd = As + (stage % 3) * BM * LDS_;
        __half* Bsd = Bs + (stage % 3) * BN * LDS_;
        const int k0 = stage * BK;
#pragma unroll
        for (int c = tid; c < A_CH; c += THREADS) {
            int r = c / CPR, cc = (c % CPR) * 8;
            uint32_t sdst = (uint32_t)__cvta_generic_to_shared(&Asd[r * LDS_ + cc]);
            const __half* src = &A[(size_t)(bm + r) * K + k0 + cc];
            asm volatile("cp.async.cg.shared.global [%0], [%1], 16;" :: "r"(sdst), "l"(src));
        }
#pragma unroll
        for (int c = tid; c < B_CH; c += THREADS) {
            int r = c / CPR, cc = (c % CPR) * 8;
            uint32_t sdst = (uint32_t)__cvta_generic_to_shared(&Bsd[r * LDS_ + cc]);
            const __half* src = &B[(size_t)(bn + r) * K + k0 + cc];
            asm volatile("cp.async.cg.shared.global [%0], [%1], 16;" :: "r"(sdst), "l"(src));
        }
        asm volatile("cp.async.commit_group;");
    };

    float acc[MI][NI][4];
#pragma unroll
    for (int i = 0; i < MI; i++)
#pragma unroll
        for (int j = 0; j < NI; j++)
#pragma unroll
            for (int k = 0; k < 4; k++) acc[i][j][k] = 0.f;

    load_stage(0);
    if (NK > 1) load_stage(1);

    const int a_row = lane % 16;
    const int a_col = (lane / 16) * 8;
    const int b_t   = lane & 15;
    const int b_row = b_t % 8;
    const int b_col = (b_t / 8) * 8;

    for (int kt = 0; kt < NK; kt++) {
        if (kt + 1 < NK) {
            asm volatile("cp.async.wait_group 1;");
        } else {
            asm volatile("cp.async.wait_group 0;");
        }
        __syncthreads();

        if (kt + 2 < NK) load_stage(kt + 2);

        __half* Asb = As + (kt % 3) * BM * LDS_;
        __half* Bsb = Bs + (kt % 3) * BN * LDS_;

#pragma unroll
        for (int kk = 0; kk < BK; kk += 16) {
            uint32_t af[MI][4];
#pragma unroll
            for (int mi = 0; mi < MI; mi++) {
                uint32_t addr = (uint32_t)__cvta_generic_to_shared(
                    &Asb[(wm + mi * 16 + a_row) * LDS_ + kk + a_col]);
                asm volatile("ldmatrix.sync.aligned.m8n8.x4.shared.b16 {%0,%1,%2,%3}, [%4];"
                             : "=r"(af[mi][0]), "=r"(af[mi][1]), "=r"(af[mi][2]), "=r"(af[mi][3])
                             : "r"(addr));
            }
            uint32_t bf[NI][2];
#pragma unroll
            for (int ni = 0; ni < NI; ni++) {
                uint32_t addr = (uint32_t)__cvta_generic_to_shared(
                    &Bsb[(wn + ni * 8 + b_row) * LDS_ + kk + b_col]);
                asm volatile("ldmatrix.sync.aligned.m8n8.x2.shared.b16 {%0,%1}, [%2];"
                             : "=r"(bf[ni][0]), "=r"(bf[ni][1])
                             : "r"(addr));
            }
#pragma unroll
            for (int mi = 0; mi < MI; mi++) {
#pragma unroll
                for (int ni = 0; ni < NI; ni++) {
                    asm volatile(
                        "mma.sync.aligned.m16n8k16.row.col.f32.f16.f16.f32 "
                        "{%0,%1,%2,%3}, {%4,%5,%6,%7}, {%8,%9}, {%0,%1,%2,%3};"
                        : "+f"(acc[mi][ni][0]), "+f"(acc[mi][ni][1]),
                          "+f"(acc[mi][ni][2]), "+f"(acc[mi][ni][3])
                        : "r"(af[mi][0]), "r"(af[mi][1]), "r"(af[mi][2]), "r"(af[mi][3]),
                          "r"(bf[ni][0]), "r"(bf[ni][1]));
                }
            }
        }
    }

#pragma unroll
    for (int mi = 0; mi < MI; mi++) {
        int row0 = bm + wm + mi * 16 + lane / 4;
#pragma unroll
        for (int ni = 0; ni < NI; ni++) {
            int col = bn + wn + ni * 8 + 2 * (lane % 4);
            float2 bv = *(const float2*)&bias[col];
            float2 v0 = make_float2(acc[mi][ni][0] + bv.x, acc[mi][ni][1] + bv.y);
            float2 v1 = make_float2(acc[mi][ni][2] + bv.x, acc[mi][ni][3] + bv.y);
            *(float2*)&C[(size_t)row0 * N + col] = v0;
            *(float2*)&C[(size_t)(row0 + 8) * N + col] = v1;
        }
    }
}

// smem sizes (3 stages)
#define DSM_BIG   (3 * (128 + 128) * (64 + 8) * 2)   // 110592 (2 CTA/SM)
#define DSM_SMALL (3 * (64 + 64) * (64 + 8) * 2)     // 55296

#define GEMM_BIG   gemm_fp16_bias<128, 128, 64, 64, 32, 2>
#define GEMM_SMALL gemm_fp16_bias<64, 64, 64, 32, 32, 4>

// ---------------- setup / conversion kernels ----------------
__global__ void init_tokens_kernel(const int* __restrict__ target)
{
    int b = threadIdx.x;
    g_tokens[b * Tq + 0] = 0;  // SOS
    for (int t = 1; t < Tq; t++) g_tokens[b * Tq + t] = target[b * Tq + t - 1];
}

__global__ void f2h_kernel(const float* __restrict__ src, __half* __restrict__ dst, int n4)
{
    int i = blockIdx.x * blockDim.x + threadIdx.x;
    if (i >= n4) return;
    float4 v = ((const float4*)src)[i];
    __half2 lo = __floats2half2_rn(v.x, v.y);
    __half2 hi = __floats2half2_rn(v.z, v.w);
    uint2 o;
    o.x = *(uint32_t*)&lo;
    o.y = *(uint32_t*)&hi;
    ((uint2*)dst)[i] = o;
}

__global__ void slice_h_kernel(const float* __restrict__ src, __half* __restrict__ dst,
                               int N, int K, int stride, int off)
{
    int i = blockIdx.x * blockDim.x + threadIdx.x;
    if (i >= N * K) return;
    int n = i / K, k = i % K;
    dst[i] = __float2half_rn(src[(size_t)n * stride + off + k]);
}

__global__ void emb_h_kernel(const float* __restrict__ emb)
{
    int i = blockIdx.x * blockDim.x + threadIdx.x;
    int r = i / Hq, j = i % Hq;
    int t = r / Bq, b = r % Bq;
    g_e_h[i] = __float2half_rn(emb[(size_t)g_tokens[b * Tq + t] * Hq + j]);
}

__global__ void bias_cat_kernel(const float* __restrict__ bua, const float* __restrict__ bhh,
                                const float* __restrict__ ba)
{
    int i = blockIdx.x * blockDim.x + threadIdx.x;  // 4096
    g_bcat[i] = (i < Hq) ? bua[i] : bhh[i - Hq];
    g_bkA[i]  = (i < Hq) ? ba[i] : 0.f;
}

__global__ void copy_h0_kernel(float* __restrict__ dst, const float* __restrict__ src)
{
    int i = blockIdx.x * blockDim.x + threadIdx.x;
    float v = src[i];
    dst[i] = v;
    g_h_h[i] = __float2half_rn(v);
}

__global__ void copy_kernel(float* __restrict__ dst, const float* __restrict__ src)
{
    int i = blockIdx.x * blockDim.x + threadIdx.x;
    dst[i] = src[i];
}

// ---------------- fused attention + GRU ----------------
__global__ void __launch_bounds__(128)
attn_gru_kernel(const float* __restrict__ Va, const float* __restrict__ bva,
                float* __restrict__ att_out,
                const float* __restrict__ hcur, float* __restrict__ hnext, int t)
{
    const int b = blockIdx.x;
    const int tid = threadIdx.x;

    float partial[Sq];
#pragma unroll
    for (int s = 0; s < Sq; s++) partial[s] = 0.f;

    for (int h = tid; h < Hq; h += 128) {
        float qv = g_qgh[b * 4096 + h];
        float va = Va[h];
#pragma unroll
        for (int s = 0; s < Sq; s++) {
            float kw = g_keysA[((size_t)b * Sq + s) * 4096 + h];
            partial[s] += va * tanhf(kw + qv);
        }
    }

    __shared__ float red[4][Sq];
    __shared__ float w[Sq];
    __shared__ float gic_s[3 * Hq];
    int lane = tid & 31, warp = tid >> 5;
#pragma unroll
    for (int s = 0; s < Sq; s++) {
        float v = partial[s];
#pragma unroll
        for (int o = 16; o > 0; o >>= 1) v += __shfl_xor_sync(0xffffffffu, v, o);
        if (lane == 0) red[warp][s] = v;
    }
    __syncthreads();

    if (tid == 0) {
        float scv[Sq], mx = -1e30f;
#pragma unroll
        for (int s = 0; s < Sq; s++) {
            scv[s] = red[0][s] + red[1][s] + red[2][s] + red[3][s] + bva[0];
            mx = fmaxf(mx, scv[s]);
        }
        float sum = 0.f;
#pragma unroll
        for (int s = 0; s < Sq; s++) { scv[s] = expf(scv[s] - mx); sum += scv[s]; }
        float inv = 1.f / sum;
#pragma unroll
        for (int s = 0; s < Sq; s++) w[s] = scv[s] * inv;
    }
    __syncthreads();

    if (tid < Sq) att_out[(size_t)b * (Tq * Sq) + t * Sq + tid] = w[tid];

    const float* kA = g_keysA + (size_t)b * Sq * 4096 + 1024;
    for (int j = tid; j < 3 * Hq; j += 128) {
        float acc = 0.f;
#pragma unroll
        for (int s = 0; s < Sq; s++)
            acc += w[s] * kA[(size_t)s * 4096 + j];
        gic_s[j] = acc;
    }
    __syncthreads();

    const float* gie = g_gie + (size_t)(t * Bq + b) * 3 * Hq;
    const float* gh  = g_qgh + (size_t)b * 4096 + Hq;
    for (int j = tid; j < Hq; j += 128) {
        float r = 1.f / (1.f + expf(-(gie[j] + gic_s[j] + gh[j])));
        float z = 1.f / (1.f + expf(-(gie[Hq + j] + gic_s[Hq + j] + gh[Hq + j])));
        float n = tanhf(gie[2 * Hq + j] + gic_s[2 * Hq + j] + r * gh[2 * Hq + j]);
        float hv = (1.f - z) * n + z * hcur[b * Hq + j];
        hnext[b * Hq + j] = hv;
        __half hh = __float2half_rn(hv);
        g_hall[(size_t)(t * Bq + b) * Hq + j] = hh;
        g_h_h[b * Hq + j] = hh;
    }
}

// ---------------- log_softmax for one step slice (256 rows) ----------------
__global__ void __launch_bounds__(256)
logsoftmax_slice_kernel(float* __restrict__ out, int t)
{
    const int b = blockIdx.x, tid = threadIdx.x;
    const float* row = g_logits_all + (size_t)(t * Bq + b) * Vq;

    float m = -1e30f, s = 0.f;
    for (int v = tid; v < Vq; v += 256) {
        float x = row[v];
        float nm = fmaxf(m, x);
        s = s * expf(m - nm) + expf(x - nm);
        m = nm;
    }
    int lane = tid & 31, warp = tid >> 5;
#pragma unroll
    for (int o = 16; o > 0; o >>= 1) {
        float m2 = __shfl_xor_sync(0xffffffffu, m, o);
        float s2 = __shfl_xor_sync(0xffffffffu, s, o);
        float nm = fmaxf(m, m2);
        s = s * expf(m - nm) + s2 * expf(m2 - nm);
        m = nm;
    }
    __shared__ float sm[8], ss[8];
    __shared__ float lse_sh;
    if (lane == 0) { sm[warp] = m; ss[warp] = s; }
    __syncthreads();
    if (tid == 0) {
        float M = sm[0], S = ss[0];
#pragma unroll
        for (int i = 1; i < 8; i++) {
            float nm = fmaxf(M, sm[i]);
            S = S * expf(M - nm) + ss[i] * expf(sm[i] - nm);
            M = nm;
        }
        lse_sh = M + logf(S);
    }
    __syncthreads();
    float lse = lse_sh;
    float* orow = out + ((size_t)b * Tq + t) * Vq;
    for (int v = tid; v < Vq; v += 256) orow[v] = row[v] - lse;
}

// ---------------- launch ----------------
extern "C" void kernel_launch(void* const* d_in, const int* in_sizes, int n_in,
                              void* d_out, int out_size)
{
    const float* enc_out = (const float*)d_in[0];
    const float* enc_hid = (const float*)d_in[1];
    const int*   target  = (const int*)  d_in[2];
    const float* emb     = (const float*)d_in[3];
    const float* Wa      = (const float*)d_in[4];
    const float* ba      = (const float*)d_in[5];
    const float* Ua      = (const float*)d_in[6];
    const float* bua     = (const float*)d_in[7];
    const float* Va      = (const float*)d_in[8];
    const float* bva     = (const float*)d_in[9];
    const float* W_ih    = (const float*)d_in[10];
    const float* W_hh    = (const float*)d_in[11];
    const float* b_ih    = (const float*)d_in[12];
    const float* b_hh    = (const float*)d_in[13];
    const float* W_out   = (const float*)d_in[14];
    const float* b_out   = (const float*)d_in[15];

    float* out = (float*)d_out;
    const size_t HID_OFF = (size_t)Bq * Tq * Vq;
    const size_t ATT_OFF = HID_OFF + (size_t)Bq * Hq;

    float *keysA, *gie, *h0, *h1, *logitsA, *bcat, *bkA, *qgh;
    __half *enc_h, *e_h, *WkA, *Wqh, *We, *h_h, *hall, *Wout_h;
    cudaGetSymbolAddress((void**)&keysA, g_keysA);
    cudaGetSymbolAddress((void**)&gie, g_gie);
    cudaGetSymbolAddress((void**)&h0, g_h0);
    cudaGetSymbolAddress((void**)&h1, g_h1);
    cudaGetSymbolAddress((void**)&logitsA, g_logits_all);
    cudaGetSymbolAddress((void**)&bcat, g_bcat);
    cudaGetSymbolAddress((void**)&bkA, g_bkA);
    cudaGetSymbolAddress((void**)&qgh, g_qgh);
    cudaGetSymbolAddress((void**)&enc_h, g_enc_h);
    cudaGetSymbolAddress((void**)&e_h, g_e_h);
    cudaGetSymbolAddress((void**)&WkA, g_WkA);
    cudaGetSymbolAddress((void**)&Wqh, g_Wqh);
    cudaGetSymbolAddress((void**)&We, g_We);
    cudaGetSymbolAddress((void**)&h_h, g_h_h);
    cudaGetSymbolAddress((void**)&hall, g_hall);
    cudaGetSymbolAddress((void**)&Wout_h, g_Wout_h);

    cudaFuncSetAttribute((const void*)GEMM_BIG,
                         cudaFuncAttributeMaxDynamicSharedMemorySize, DSM_BIG);
    cudaFuncSetAttribute((const void*)GEMM_SMALL,
                         cudaFuncAttributeMaxDynamicSharedMemorySize, DSM_SMALL);

    // streams/events created once, outside graph capture (first call is the
    // uncaptured correctness run). Reused identically on every call.
    static cudaStream_t s_log = 0, s_sm = 0;
    static cudaEvent_t evH[Tq], evL[Tq], evFork, evDone;
    static bool inited = false;
    if (!inited) {
        cudaStreamCreateWithFlags(&s_log, cudaStreamNonBlocking);
        cudaStreamCreateWithFlags(&s_sm, cudaStreamNonBlocking);
        for (int t = 0; t < Tq; t++) {
            cudaEventCreateWithFlags(&evH[t], cudaEventDisableTiming);
            cudaEventCreateWithFlags(&evL[t], cudaEventDisableTiming);
        }
        cudaEventCreateWithFlags(&evFork, cudaEventDisableTiming);
        cudaEventCreateWithFlags(&evDone, cudaEventDisableTiming);
        inited = true;
    }

    // ---- setup on main stream ----
    init_tokens_kernel<<<1, 256>>>(target);
    emb_h_kernel<<<(BT * Hq) / 256, 256>>>(emb);
    slice_h_kernel<<<(3 * Hq * Hq + 255) / 256, 256>>>(W_ih, We, 3 * Hq, Hq, 2 * Hq, 0);
    // gi_e all steps = E @ W_e^T + b_ih  (M=2560, N=3072, K=1024)
    GEMM_BIG<<<dim3(3 * Hq / 128, BT / 128), 256, DSM_BIG>>>(
        e_h, We, b_ih, gie, BT, 3 * Hq, Hq);

    // fork side stream: W_out fp16 convert happens concurrently with setup
    cudaEventRecord(evFork, 0);
    cudaStreamWaitEvent(s_log, evFork, 0);
    f2h_kernel<<<(Vq * Hq / 4 + 255) / 256, 256, 0, s_log>>>(W_out, Wout_h, Vq * Hq / 4);

    f2h_kernel<<<(Bq * Sq * Hq / 4 + 255) / 256, 256>>>(enc_out, enc_h, Bq * Sq * Hq / 4);
    f2h_kernel<<<(Hq * Hq / 4 + 255) / 256, 256>>>(Wa, WkA, Hq * Hq / 4);
    slice_h_kernel<<<(3 * Hq * Hq + 255) / 256, 256>>>(W_ih, WkA + (size_t)Hq * Hq,
                                                       3 * Hq, Hq, 2 * Hq, Hq);
    bias_cat_kernel<<<16, 256>>>(bua, b_hh, ba);
    // keysA = enc @ [Wa;Wc]^T + [ba|0]  (M=2560, N=4096, K=1024)
    GEMM_BIG<<<dim3(4096 / 128, (Bq * Sq) / 128), 256, DSM_BIG>>>(
        enc_h, WkA, bkA, keysA, Bq * Sq, 4096, Hq);

    copy_h0_kernel<<<(Bq * Hq) / 256, 256>>>(h0, enc_hid);
    f2h_kernel<<<(Hq * Hq / 4 + 255) / 256, 256>>>(Ua, Wqh, Hq * Hq / 4);
    f2h_kernel<<<(3 * Hq * Hq / 4 + 255) / 256, 256>>>(W_hh, Wqh + (size_t)Hq * Hq,
                                                       3 * Hq * Hq / 4);

    float* hcur = h0;
    float* hnext = h1;
    for (int t = 0; t < Tq; t++) {
        // [q | gh] = h @ [Ua; W_hh]^T + [bua | b_hh]  (M=256, N=4096, K=1024)
        GEMM_SMALL<<<dim3(4096 / 64, Bq / 64), 128, DSM_SMALL>>>(
            h_h, Wqh, bcat, qgh, Bq, 4096, Hq);
        attn_gru_kernel<<<Bq, 128>>>(Va, bva, out + ATT_OFF, hcur, hnext, t);
        cudaEventRecord(evH[t], 0);

        // overlapped logits slice for step t on s_log
        cudaStreamWaitEvent(s_log, evH[t], 0);
        GEMM_BIG<<<dim3(Vq / 128, Bq / 128), 256, DSM_BIG, s_log>>>(
            hall + (size_t)t * Bq * Hq, Wout_h, b_out,
            logitsA + (size_t)t * Bq * Vq, Bq, Vq, Hq);
        cudaEventRecord(evL[t], s_log);

        // overlapped log_softmax slice on s_sm
        cudaStreamWaitEvent(s_sm, evL[t], 0);
        logsoftmax_slice_kernel<<<Bq, 256, 0, s_sm>>>(out, t);

        float* tmp = hcur; hcur = hnext; hnext = tmp;
    }

    // h_last on main stream
    copy_kernel<<<(Bq * Hq) / 256, 256>>>(out + HID_OFF, hcur);

    // join: main stream waits for the last softmax (s_sm is in-order)
    cudaEventRecord(evDone, s_sm);
    cudaStreamWaitEvent(0, evDone, 0);
}

// round 15
// speedup vs baseline: 1.4226x; 1.1644x over previous
#include <cuda_runtime.h>
#include <cuda_fp16.h>
#include <math.h>
#include <stdint.h>

#define Bq 256
#define Sq 10
#define Hq 1024
#define Vq 32000
#define Tq 10
#define BT (Bq * Tq)

// ---------------- device scratch (no allocation) ----------------
__device__ __align__(16) float g_keysA[(size_t)Bq * Sq * 4096];  // [ keysW(1024) | keysC(3072) ]
__device__ int   g_tokens[Bq * Tq];
__device__ __align__(16) float g_qgh[Bq * 4096];
__device__ __align__(16) float g_gie[(size_t)BT * 3 * Hq];
__device__ __align__(16) float g_h0[Bq * Hq];
__device__ __align__(16) float g_h1[Bq * Hq];
__device__ __align__(16) float g_logits_all[(size_t)BT * Vq];
__device__ __align__(16) float g_bcat[4096];
__device__ __align__(16) float g_bkA[4096];

__device__ __align__(16) __half g_enc_h[(size_t)Bq * Sq * Hq];
__device__ __align__(16) __half g_e_h[(size_t)BT * Hq];
__device__ __align__(16) __half g_WkA[(size_t)4096 * Hq];   // [Wa; Wc]
__device__ __align__(16) __half g_Wqh[(size_t)4096 * Hq];   // [Ua; Whh]
__device__ __align__(16) __half g_We[(size_t)3 * Hq * Hq];
__device__ __align__(16) __half g_h_h[Bq * Hq];
__device__ __align__(16) __half g_hall[(size_t)BT * Hq];
__device__ __align__(16) __half g_Wout_h[(size_t)Vq * Hq];

// ---------------- fp16 HMMA GEMM: 3-stage cp.async ring ----------------
template <int BM, int BN, int BK, int WM, int WN, int MINB>
__global__ void __launch_bounds__((BM / WM) * (BN / WN) * 32, MINB)
gemm_fp16_bias(const __half* __restrict__ A, const __half* __restrict__ B,
               const float* __restrict__ bias, float* __restrict__ C,
               int M, int N, int K)
{
    constexpr int WARPS_M = BM / WM;
    constexpr int WARPS_N = BN / WN;
    constexpr int THREADS = WARPS_M * WARPS_N * 32;
    constexpr int PAD = 8;
    constexpr int LDS_ = BK + PAD;
    constexpr int MI = WM / 16;
    constexpr int NI = WN / 8;

    extern __shared__ char smem_raw[];
    __half* As = (__half*)smem_raw;
    __half* Bs = (__half*)(smem_raw + 3 * BM * LDS_ * 2);

    const int tid = threadIdx.x;
    const int wid = tid / 32, lane = tid % 32;
    const int wm = (wid / WARPS_N) * WM;
    const int wn = (wid % WARPS_N) * WN;
    const int bm = blockIdx.y * BM;
    const int bn = blockIdx.x * BN;

    constexpr int A_CH = BM * BK / 8;
    constexpr int B_CH = BN * BK / 8;
    constexpr int CPR = BK / 8;

    const int NK = K / BK;

    auto load_stage = [&](int stage) {
        __half* Asd = As + (stage % 3) * BM * LDS_;
        __half* Bsd = Bs + (stage % 3) * BN * LDS_;
        const int k0 = stage * BK;
#pragma unroll
        for (int c = tid; c < A_CH; c += THREADS) {
            int r = c / CPR, cc = (c % CPR) * 8;
            uint32_t sdst = (uint32_t)__cvta_generic_to_shared(&Asd[r * LDS_ + cc]);
            const __half* src = &A[(size_t)(bm + r) * K + k0 + cc];
            asm volatile("cp.async.cg.shared.global [%0], [%1], 16;" :: "r"(sdst), "l"(src));
        }
#pragma unroll
        for (int c = tid; c < B_CH; c += THREADS) {
            int r = c / CPR, cc = (c % CPR) * 8;
            uint32_t sdst = (uint32_t)__cvta_generic_to_shared(&Bsd[r * LDS_ + cc]);
            const __half* src = &B[(size_t)(bn + r) * K + k0 + cc];
            asm volatile("cp.async.cg.shared.global [%0], [%1], 16;" :: "r"(sdst), "l"(src));
        }
        asm volatile("cp.async.commit_group;");
    };

    float acc[MI][NI][4];
#pragma unroll
    for (int i = 0; i < MI; i++)
#pragma unroll
        for (int j = 0; j < NI; j++)
#pragma unroll
            for (int k = 0; k < 4; k++) acc[i][j][k] = 0.f;

    load_stage(0);
    if (NK > 1) load_stage(1);

    const int a_row = lane % 16;
    const int a_col = (lane / 16) * 8;
    const int b_t   = lane & 15;
    const int b_row = b_t % 8;
    const int b_col = (b_t / 8) * 8;

    for (int kt = 0; kt < NK; kt++) {
        if (kt + 1 < NK) {
            asm volatile("cp.async.wait_group 1;");
        } else {
            asm volatile("cp.async.wait_group 0;");
        }
        __syncthreads();

        if (kt + 2 < NK) load_stage(kt + 2);

        __half* Asb = As + (kt % 3) * BM * LDS_;
        __half* Bsb = Bs + (kt % 3) * BN * LDS_;

#pragma unroll
        for (int kk = 0; kk < BK; kk += 16) {
            uint32_t af[MI][4];
#pragma unroll
            for (int mi = 0; mi < MI; mi++) {
                uint32_t addr = (uint32_t)__cvta_generic_to_shared(
                    &Asb[(wm + mi * 16 + a_row) * LDS_ + kk + a_col]);
                asm volatile("ldmatrix.sync.aligned.m8n8.x4.shared.b16 {%0,%1,%2,%3}, [%4];"
                             : "=r"(af[mi][0]), "=r"(af[mi][1]), "=r"(af[mi][2]), "=r"(af[mi][3])
                             : "r"(addr));
            }
            uint32_t bf[NI][2];
#pragma unroll
            for (int ni = 0; ni < NI; ni++) {
                uint32_t addr = (uint32_t)__cvta_generic_to_shared(
                    &Bsb[(wn + ni * 8 + b_row) * LDS_ + kk + b_col]);
                asm volatile("ldmatrix.sync.aligned.m8n8.x2.shared.b16 {%0,%1}, [%2];"
                             : "=r"(bf[ni][0]), "=r"(bf[ni][1])
                             : "r"(addr));
            }
#pragma unroll
            for (int mi = 0; mi < MI; mi++) {
#pragma unroll
                for (int ni = 0; ni < NI; ni++) {
                    asm volatile(
                        "mma.sync.aligned.m16n8k16.row.col.f32.f16.f16.f32 "
                        "{%0,%1,%2,%3}, {%4,%5,%6,%7}, {%8,%9}, {%0,%1,%2,%3};"
                        : "+f"(acc[mi][ni][0]), "+f"(acc[mi][ni][1]),
                          "+f"(acc[mi][ni][2]), "+f"(acc[mi][ni][3])
                        : "r"(af[mi][0]), "r"(af[mi][1]), "r"(af[mi][2]), "r"(af[mi][3]),
                          "r"(bf[ni][0]), "r"(bf[ni][1]));
                }
            }
        }
    }

#pragma unroll
    for (int mi = 0; mi < MI; mi++) {
        int row0 = bm + wm + mi * 16 + lane / 4;
#pragma unroll
        for (int ni = 0; ni < NI; ni++) {
            int col = bn + wn + ni * 8 + 2 * (lane % 4);
            float2 bv = *(const float2*)&bias[col];
            float2 v0 = make_float2(acc[mi][ni][0] + bv.x, acc[mi][ni][1] + bv.y);
            float2 v1 = make_float2(acc[mi][ni][2] + bv.x, acc[mi][ni][3] + bv.y);
            *(float2*)&C[(size_t)row0 * N + col] = v0;
            *(float2*)&C[(size_t)(row0 + 8) * N + col] = v1;
        }
    }
}

// smem sizes (3 stages)
#define DSM_BIG   (3 * (128 + 128) * (64 + 8) * 2)   // 110592 (2 CTA/SM)
#define DSM_SMALL (3 * (64 + 64) * (64 + 8) * 2)     // 55296

#define GEMM_BIG   gemm_fp16_bias<128, 128, 64, 64, 32, 2>
#define GEMM_SMALL gemm_fp16_bias<64, 64, 64, 32, 32, 4>

// ---------------- setup / conversion kernels ----------------
__global__ void init_tokens_kernel(const int* __restrict__ target)
{
    int b = threadIdx.x;
    g_tokens[b * Tq + 0] = 0;  // SOS
    for (int t = 1; t < Tq; t++) g_tokens[b * Tq + t] = target[b * Tq + t - 1];
}

__global__ void f2h_kernel(const float* __restrict__ src, __half* __restrict__ dst, int n4)
{
    int i = blockIdx.x * blockDim.x + threadIdx.x;
    if (i >= n4) return;
    float4 v = ((const float4*)src)[i];
    __half2 lo = __floats2half2_rn(v.x, v.y);
    __half2 hi = __floats2half2_rn(v.z, v.w);
    uint2 o;
    o.x = *(uint32_t*)&lo;
    o.y = *(uint32_t*)&hi;
    ((uint2*)dst)[i] = o;
}

__global__ void slice_h_kernel(const float* __restrict__ src, __half* __restrict__ dst,
                               int N, int K, int stride, int off)
{
    int i = blockIdx.x * blockDim.x + threadIdx.x;
    if (i >= N * K) return;
    int n = i / K, k = i % K;
    dst[i] = __float2half_rn(src[(size_t)n * stride + off + k]);
}

__global__ void emb_h_kernel(const float* __restrict__ emb)
{
    int i = blockIdx.x * blockDim.x + threadIdx.x;
    int r = i / Hq, j = i % Hq;
    int t = r / Bq, b = r % Bq;
    g_e_h[i] = __float2half_rn(emb[(size_t)g_tokens[b * Tq + t] * Hq + j]);
}

__global__ void bias_cat_kernel(const float* __restrict__ bua, const float* __restrict__ bhh,
                                const float* __restrict__ ba)
{
    int i = blockIdx.x * blockDim.x + threadIdx.x;  // 4096
    g_bcat[i] = (i < Hq) ? bua[i] : bhh[i - Hq];
    g_bkA[i]  = (i < Hq) ? ba[i] : 0.f;
}

__global__ void copy_h0_kernel(float* __restrict__ dst, const float* __restrict__ src)
{
    int i = blockIdx.x * blockDim.x + threadIdx.x;
    float v = src[i];
    dst[i] = v;
    g_h_h[i] = __float2half_rn(v);
}

__global__ void copy_kernel(float* __restrict__ dst, const float* __restrict__ src)
{
    int i = blockIdx.x * blockDim.x + threadIdx.x;
    dst[i] = src[i];
}

// ---------------- fused attention + GRU ----------------
__global__ void __launch_bounds__(128)
attn_gru_kernel(const float* __restrict__ Va, const float* __restrict__ bva,
                float* __restrict__ att_out,
                const float* __restrict__ hcur, float* __restrict__ hnext, int t)
{
    const int b = blockIdx.x;
    const int tid = threadIdx.x;

    float partial[Sq];
#pragma unroll
    for (int s = 0; s < Sq; s++) partial[s] = 0.f;

    for (int h = tid; h < Hq; h += 128) {
        float qv = g_qgh[b * 4096 + h];
        float va = Va[h];
#pragma unroll
        for (int s = 0; s < Sq; s++) {
            float kw = g_keysA[((size_t)b * Sq + s) * 4096 + h];
            partial[s] += va * tanhf(kw + qv);
        }
    }

    __shared__ float red[4][Sq];
    __shared__ float w[Sq];
    __shared__ float gic_s[3 * Hq];
    int lane = tid & 31, warp = tid >> 5;
#pragma unroll
    for (int s = 0; s < Sq; s++) {
        float v = partial[s];
#pragma unroll
        for (int o = 16; o > 0; o >>= 1) v += __shfl_xor_sync(0xffffffffu, v, o);
        if (lane == 0) red[warp][s] = v;
    }
    __syncthreads();

    if (tid == 0) {
        float scv[Sq], mx = -1e30f;
#pragma unroll
        for (int s = 0; s < Sq; s++) {
            scv[s] = red[0][s] + red[1][s] + red[2][s] + red[3][s] + bva[0];
            mx = fmaxf(mx, scv[s]);
        }
        float sum = 0.f;
#pragma unroll
        for (int s = 0; s < Sq; s++) { scv[s] = expf(scv[s] - mx); sum += scv[s]; }
        float inv = 1.f / sum;
#pragma unroll
        for (int s = 0; s < Sq; s++) w[s] = scv[s] * inv;
    }
    __syncthreads();

    if (tid < Sq) att_out[(size_t)b * (Tq * Sq) + t * Sq + tid] = w[tid];

    const float* kA = g_keysA + (size_t)b * Sq * 4096 + 1024;
    for (int j = tid; j < 3 * Hq; j += 128) {
        float acc = 0.f;
#pragma unroll
        for (int s = 0; s < Sq; s++)
            acc += w[s] * kA[(size_t)s * 4096 + j];
        gic_s[j] = acc;
    }
    __syncthreads();

    const float* gie = g_gie + (size_t)(t * Bq + b) * 3 * Hq;
    const float* gh  = g_qgh + (size_t)b * 4096 + Hq;
    for (int j = tid; j < Hq; j += 128) {
        float r = 1.f / (1.f + expf(-(gie[j] + gic_s[j] + gh[j])));
        float z = 1.f / (1.f + expf(-(gie[Hq + j] + gic_s[Hq + j] + gh[Hq + j])));
        float n = tanhf(gie[2 * Hq + j] + gic_s[2 * Hq + j] + r * gh[2 * Hq + j]);
        float hv = (1.f - z) * n + z * hcur[b * Hq + j];
        hnext[b * Hq + j] = hv;
        __half hh = __float2half_rn(hv);
        g_hall[(size_t)(t * Bq + b) * Hq + j] = hh;
        g_h_h[b * Hq + j] = hh;
    }
}

// ---------------- log_softmax over a row range [r0, r0+gridDim) ----------------
__global__ void __launch_bounds__(256)
logsoftmax_range_kernel(float* __restrict__ out, int r0)
{
    const int r = r0 + blockIdx.x, tid = threadIdx.x;
    const int t = r / Bq, b = r % Bq;
    const float* row = g_logits_all + (size_t)r * Vq;

    float m = -1e30f, s = 0.f;
    for (int v = tid; v < Vq; v += 256) {
        float x = row[v];
        float nm = fmaxf(m, x);
        s = s * expf(m - nm) + expf(x - nm);
        m = nm;
    }
    int lane = tid & 31, warp = tid >> 5;
#pragma unroll
    for (int o = 16; o > 0; o >>= 1) {
        float m2 = __shfl_xor_sync(0xffffffffu, m, o);
        float s2 = __shfl_xor_sync(0xffffffffu, s, o);
        float nm = fmaxf(m, m2);
        s = s * expf(m - nm) + s2 * expf(m2 - nm);
        m = nm;
    }
    __shared__ float sm[8], ss[8];
    __shared__ float lse_sh;
    if (lane == 0) { sm[warp] = m; ss[warp] = s; }
    __syncthreads();
    if (tid == 0) {
        float M = sm[0], S = ss[0];
#pragma unroll
        for (int i = 1; i < 8; i++) {
            float nm = fmaxf(M, sm[i]);
            S = S * expf(M - nm) + ss[i] * expf(sm[i] - nm);
            M = nm;
        }
        lse_sh = M + logf(S);
    }
    __syncthreads();
    float lse = lse_sh;
    float* orow = out + ((size_t)b * Tq + t) * Vq;
    for (int v = tid; v < Vq; v += 256) orow[v] = row[v] - lse;
}

// ---------------- launch ----------------
extern "C" void kernel_launch(void* const* d_in, const int* in_sizes, int n_in,
                              void* d_out, int out_size)
{
    const float* enc_out = (const float*)d_in[0];
    const float* enc_hid = (const float*)d_in[1];
    const int*   target  = (const int*)  d_in[2];
    const float* emb     = (const float*)d_in[3];
    const float* Wa      = (const float*)d_in[4];
    const float* ba      = (const float*)d_in[5];
    const float* Ua      = (const float*)d_in[6];
    const float* bua     = (const float*)d_in[7];
    const float* Va      = (const float*)d_in[8];
    const float* bva     = (const float*)d_in[9];
    const float* W_ih    = (const float*)d_in[10];
    const float* W_hh    = (const float*)d_in[11];
    const float* b_ih    = (const float*)d_in[12];
    const float* b_hh    = (const float*)d_in[13];
    const float* W_out   = (const float*)d_in[14];
    const float* b_out   = (const float*)d_in[15];

    float* out = (float*)d_out;
    const size_t HID_OFF = (size_t)Bq * Tq * Vq;
    const size_t ATT_OFF = HID_OFF + (size_t)Bq * Hq;

    float *keysA, *gie, *h0, *h1, *logitsA, *bcat, *bkA, *qgh;
    __half *enc_h, *e_h, *WkA, *Wqh, *We, *h_h, *hall, *Wout_h;
    cudaGetSymbolAddress((void**)&keysA, g_keysA);
    cudaGetSymbolAddress((void**)&gie, g_gie);
    cudaGetSymbolAddress((void**)&h0, g_h0);
    cudaGetSymbolAddress((void**)&h1, g_h1);
    cudaGetSymbolAddress((void**)&logitsA, g_logits_all);
    cudaGetSymbolAddress((void**)&bcat, g_bcat);
    cudaGetSymbolAddress((void**)&bkA, g_bkA);
    cudaGetSymbolAddress((void**)&qgh, g_qgh);
    cudaGetSymbolAddress((void**)&enc_h, g_enc_h);
    cudaGetSymbolAddress((void**)&e_h, g_e_h);
    cudaGetSymbolAddress((void**)&WkA, g_WkA);
    cudaGetSymbolAddress((void**)&Wqh, g_Wqh);
    cudaGetSymbolAddress((void**)&We, g_We);
    cudaGetSymbolAddress((void**)&h_h, g_h_h);
    cudaGetSymbolAddress((void**)&hall, g_hall);
    cudaGetSymbolAddress((void**)&Wout_h, g_Wout_h);

    cudaFuncSetAttribute((const void*)GEMM_BIG,
                         cudaFuncAttributeMaxDynamicSharedMemorySize, DSM_BIG);
    cudaFuncSetAttribute((const void*)GEMM_SMALL,
                         cudaFuncAttributeMaxDynamicSharedMemorySize, DSM_SMALL);

    static cudaStream_t s_log = 0, s_sm = 0;
    static cudaEvent_t evFork, evH5, evGA, evSm;
    static bool inited = false;
    if (!inited) {
        cudaStreamCreateWithFlags(&s_log, cudaStreamNonBlocking);
        cudaStreamCreateWithFlags(&s_sm, cudaStreamNonBlocking);
        cudaEventCreateWithFlags(&evFork, cudaEventDisableTiming);
        cudaEventCreateWithFlags(&evH5, cudaEventDisableTiming);
        cudaEventCreateWithFlags(&evGA, cudaEventDisableTiming);
        cudaEventCreateWithFlags(&evSm, cudaEventDisableTiming);
        inited = true;
    }

    // ---- setup ----
    init_tokens_kernel<<<1, 256>>>(target);
    // side stream: W_out convert (big, independent) overlapped with setup
    cudaEventRecord(evFork, 0);
    cudaStreamWaitEvent(s_log, evFork, 0);
    f2h_kernel<<<(Vq * Hq / 4 + 255) / 256, 256, 0, s_log>>>(W_out, Wout_h, Vq * Hq / 4);

    emb_h_kernel<<<(BT * Hq) / 256, 256>>>(emb);
    slice_h_kernel<<<(3 * Hq * Hq + 255) / 256, 256>>>(W_ih, We, 3 * Hq, Hq, 2 * Hq, 0);
    // gi_e all steps = E @ W_e^T + b_ih  (M=2560, N=3072, K=1024)
    GEMM_BIG<<<dim3(3 * Hq / 128, BT / 128), 256, DSM_BIG>>>(
        e_h, We, b_ih, gie, BT, 3 * Hq, Hq);

    f2h_kernel<<<(Bq * Sq * Hq / 4 + 255) / 256, 256>>>(enc_out, enc_h, Bq * Sq * Hq / 4);
    f2h_kernel<<<(Hq * Hq / 4 + 255) / 256, 256>>>(Wa, WkA, Hq * Hq / 4);
    slice_h_kernel<<<(3 * Hq * Hq + 255) / 256, 256>>>(W_ih, WkA + (size_t)Hq * Hq,
                                                       3 * Hq, Hq, 2 * Hq, Hq);
    bias_cat_kernel<<<16, 256>>>(bua, b_hh, ba);
    // keysA = enc @ [Wa;Wc]^T + [ba|0]  (M=2560, N=4096, K=1024)
    GEMM_BIG<<<dim3(4096 / 128, (Bq * Sq) / 128), 256, DSM_BIG>>>(
        enc_h, WkA, bkA, keysA, Bq * Sq, 4096, Hq);

    copy_h0_kernel<<<(Bq * Hq) / 256, 256>>>(h0, enc_hid);
    f2h_kernel<<<(Hq * Hq / 4 + 255) / 256, 256>>>(Ua, Wqh, Hq * Hq / 4);
    f2h_kernel<<<(3 * Hq * Hq / 4 + 255) / 256, 256>>>(W_hh, Wqh + (size_t)Hq * Hq,
                                                       3 * Hq * Hq / 4);

    float* hcur = h0;
    float* hnext = h1;
    for (int t = 0; t < Tq; t++) {
        GEMM_SMALL<<<dim3(4096 / 64, Bq / 64), 128, DSM_SMALL>>>(
            h_h, Wqh, bcat, qgh, Bq, 4096, Hq);
        attn_gru_kernel<<<Bq, 128>>>(Va, bva, out + ATT_OFF, hcur, hnext, t);
        if (t == 4) {
            // fork: logits half-0 (steps 0..4, M=1280) overlaps steps 5..9
            cudaEventRecord(evH5, 0);
            cudaStreamWaitEvent(s_log, evH5, 0);
            GEMM_BIG<<<dim3(Vq / 128, (5 * Bq) / 128), 256, DSM_BIG, s_log>>>(
                hall, Wout_h, b_out, logitsA, 5 * Bq, Vq, Hq);
            cudaEventRecord(evGA, s_log);
            // softmax half-0 overlaps logits half-1
            cudaStreamWaitEvent(s_sm, evGA, 0);
            logsoftmax_range_kernel<<<5 * Bq, 256, 0, s_sm>>>(out, 0);
            cudaEventRecord(evSm, s_sm);
        }
        float* tmp = hcur; hcur = hnext; hnext = tmp;
    }

    // h_last early (ready after loop)
    copy_kernel<<<(Bq * Hq) / 256, 256>>>(out + HID_OFF, hcur);

    // logits half-1 (steps 5..9) on main — waits for half-0 GEMM resources naturally
    cudaStreamWaitEvent(0, evGA, 0);  // order: half-1 after half-0 completes (keeps contention bounded)
    GEMM_BIG<<<dim3(Vq / 128, (5 * Bq) / 128), 256, DSM_BIG>>>(
        hall + (size_t)5 * Bq * Hq, Wout_h, b_out,
        logitsA + (size_t)5 * Bq * Vq, 5 * Bq, Vq, Hq);
    logsoftmax_range_kernel<<<5 * Bq, 256>>>(out, 5 * Bq);

    // join softmax half-0
    cudaStreamWaitEvent(0, evSm, 0);
}

// round 16
// speedup vs baseline: 1.4927x; 1.0493x over previous
#include <cuda_runtime.h>
#include <cuda_fp16.h>
#include <math.h>
#include <stdint.h>

#define Bq 256
#define Sq 10
#define Hq 1024
#define Vq 32000
#define Tq 10
#define BT (Bq * Tq)

// ---------------- device scratch (no allocation) ----------------
__device__ __align__(16) float g_keysA[(size_t)Bq * Sq * 4096];  // [ keysW(1024) | keysC(3072) ]
__device__ int   g_tokens[Bq * Tq];
__device__ __align__(16) float g_qgh[Bq * 4096];
__device__ __align__(16) float g_gie[(size_t)BT * 3 * Hq];
__device__ __align__(16) float g_h0[Bq * Hq];
__device__ __align__(16) float g_h1[Bq * Hq];
__device__ __align__(16) float g_logits_all[(size_t)BT * Vq];
__device__ __align__(16) float g_bcat[4096];
__device__ __align__(16) float g_bkA[4096];

__device__ __align__(16) __half g_enc_h[(size_t)Bq * Sq * Hq];
__device__ __align__(16) __half g_e_h[(size_t)BT * Hq];
__device__ __align__(16) __half g_WkA[(size_t)4096 * Hq];   // [Wa; Wc]
__device__ __align__(16) __half g_Wqh[(size_t)4096 * Hq];   // [Ua; Whh]
__device__ __align__(16) __half g_We[(size_t)3 * Hq * Hq];
__device__ __align__(16) __half g_h_h[Bq * Hq];
__device__ __align__(16) __half g_hall[(size_t)BT * Hq];
__device__ __align__(16) __half g_Wout_h[(size_t)Vq * Hq];

// ---------------- fp16 HMMA GEMM: 3-stage cp.async ring ----------------
template <int BM, int BN, int BK, int WM, int WN, int MINB>
__global__ void __launch_bounds__((BM / WM) * (BN / WN) * 32, MINB)
gemm_fp16_bias(const __half* __restrict__ A, const __half* __restrict__ B,
               const float* __restrict__ bias, float* __restrict__ C,
               int M, int N, int K)
{
    constexpr int WARPS_M = BM / WM;
    constexpr int WARPS_N = BN / WN;
    constexpr int THREADS = WARPS_M * WARPS_N * 32;
    constexpr int PAD = 8;
    constexpr int LDS_ = BK + PAD;
    constexpr int MI = WM / 16;
    constexpr int NI = WN / 8;

    extern __shared__ char smem_raw[];
    __half* As = (__half*)smem_raw;
    __half* Bs = (__half*)(smem_raw + 3 * BM * LDS_ * 2);

    const int tid = threadIdx.x;
    const int wid = tid / 32, lane = tid % 32;
    const int wm = (wid / WARPS_N) * WM;
    const int wn = (wid % WARPS_N) * WN;
    const int bm = blockIdx.y * BM;
    const int bn = blockIdx.x * BN;

    constexpr int A_CH = BM * BK / 8;
    constexpr int B_CH = BN * BK / 8;
    constexpr int CPR = BK / 8;

    const int NK = K / BK;

    auto load_stage = [&](int stage) {
        __half* Asd = As + (stage % 3) * BM * LDS_;
        __half* Bsd = Bs + (stage % 3) * BN * LDS_;
        const int k0 = stage * BK;
#pragma unroll
        for (int c = tid; c < A_CH; c += THREADS) {
            int r = c / CPR, cc = (c % CPR) * 8;
            uint32_t sdst = (uint32_t)__cvta_generic_to_shared(&Asd[r * LDS_ + cc]);
            const __half* src = &A[(size_t)(bm + r) * K + k0 + cc];
            asm volatile("cp.async.cg.shared.global [%0], [%1], 16;" :: "r"(sdst), "l"(src));
        }
#pragma unroll
        for (int c = tid; c < B_CH; c += THREADS) {
            int r = c / CPR, cc = (c % CPR) * 8;
            uint32_t sdst = (uint32_t)__cvta_generic_to_shared(&Bsd[r * LDS_ + cc]);
            const __half* src = &B[(size_t)(bn + r) * K + k0 + cc];
            asm volatile("cp.async.cg.shared.global [%0], [%1], 16;" :: "r"(sdst), "l"(src));
        }
        asm volatile("cp.async.commit_group;");
    };

    float acc[MI][NI][4];
#pragma unroll
    for (int i = 0; i < MI; i++)
#pragma unroll
        for (int j = 0; j < NI; j++)
#pragma unroll
            for (int k = 0; k < 4; k++) acc[i][j][k] = 0.f;

    load_stage(0);
    if (NK > 1) load_stage(1);

    const int a_row = lane % 16;
    const int a_col = (lane / 16) * 8;
    const int b_t   = lane & 15;
    const int b_row = b_t % 8;
    const int b_col = (b_t / 8) * 8;

    for (int kt = 0; kt < NK; kt++) {
        if (kt + 1 < NK) {
            asm volatile("cp.async.wait_group 1;");
        } else {
            asm volatile("cp.async.wait_group 0;");
        }
        __syncthreads();

        if (kt + 2 < NK) load_stage(kt + 2);

        __half* Asb = As + (kt % 3) * BM * LDS_;
        __half* Bsb = Bs + (kt % 3) * BN * LDS_;

#pragma unroll
        for (int kk = 0; kk < BK; kk += 16) {
            uint32_t af[MI][4];
#pragma unroll
            for (int mi = 0; mi < MI; mi++) {
                uint32_t addr = (uint32_t)__cvta_generic_to_shared(
                    &Asb[(wm + mi * 16 + a_row) * LDS_ + kk + a_col]);
                asm volatile("ldmatrix.sync.aligned.m8n8.x4.shared.b16 {%0,%1,%2,%3}, [%4];"
                             : "=r"(af[mi][0]), "=r"(af[mi][1]), "=r"(af[mi][2]), "=r"(af[mi][3])
                             : "r"(addr));
            }
            uint32_t bf[NI][2];
#pragma unroll
            for (int ni = 0; ni < NI; ni++) {
                uint32_t addr = (uint32_t)__cvta_generic_to_shared(
                    &Bsb[(wn + ni * 8 + b_row) * LDS_ + kk + b_col]);
                asm volatile("ldmatrix.sync.aligned.m8n8.x2.shared.b16 {%0,%1}, [%2];"
                             : "=r"(bf[ni][0]), "=r"(bf[ni][1])
                             : "r"(addr));
            }
#pragma unroll
            for (int mi = 0; mi < MI; mi++) {
#pragma unroll
                for (int ni = 0; ni < NI; ni++) {
                    asm volatile(
                        "mma.sync.aligned.m16n8k16.row.col.f32.f16.f16.f32 "
                        "{%0,%1,%2,%3}, {%4,%5,%6,%7}, {%8,%9}, {%0,%1,%2,%3};"
                        : "+f"(acc[mi][ni][0]), "+f"(acc[mi][ni][1]),
                          "+f"(acc[mi][ni][2]), "+f"(acc[mi][ni][3])
                        : "r"(af[mi][0]), "r"(af[mi][1]), "r"(af[mi][2]), "r"(af[mi][3]),
                          "r"(bf[ni][0]), "r"(bf[ni][1]));
                }
            }
        }
    }

#pragma unroll
    for (int mi = 0; mi < MI; mi++) {
        int row0 = bm + wm + mi * 16 + lane / 4;
#pragma unroll
        for (int ni = 0; ni < NI; ni++) {
            int col = bn + wn + ni * 8 + 2 * (lane % 4);
            float2 bv = *(const float2*)&bias[col];
            float2 v0 = make_float2(acc[mi][ni][0] + bv.x, acc[mi][ni][1] + bv.y);
            float2 v1 = make_float2(acc[mi][ni][2] + bv.x, acc[mi][ni][3] + bv.y);
            *(float2*)&C[(size_t)row0 * N + col] = v0;
            *(float2*)&C[(size_t)(row0 + 8) * N + col] = v1;
        }
    }
}

// smem sizes (3 stages)
#define DSM_BIG   (3 * (128 + 128) * (64 + 8) * 2)   // 110592 (2 CTA/SM)
#define DSM_SMALL (3 * (64 + 64) * (64 + 8) * 2)     // 55296

#define GEMM_BIG   gemm_fp16_bias<128, 128, 64, 64, 32, 2>
#define GEMM_SMALL gemm_fp16_bias<64, 64, 64, 32, 32, 4>

// ---------------- setup / conversion kernels ----------------
__global__ void init_tokens_kernel(const int* __restrict__ target)
{
    int b = threadIdx.x;
    g_tokens[b * Tq + 0] = 0;  // SOS
    for (int t = 1; t < Tq; t++) g_tokens[b * Tq + t] = target[b * Tq + t - 1];
}

__global__ void f2h_kernel(const float* __restrict__ src, __half* __restrict__ dst, int n4)
{
    int i = blockIdx.x * blockDim.x + threadIdx.x;
    if (i >= n4) return;
    float4 v = ((const float4*)src)[i];
    __half2 lo = __floats2half2_rn(v.x, v.y);
    __half2 hi = __floats2half2_rn(v.z, v.w);
    uint2 o;
    o.x = *(uint32_t*)&lo;
    o.y = *(uint32_t*)&hi;
    ((uint2*)dst)[i] = o;
}

__global__ void slice_h_kernel(const float* __restrict__ src, __half* __restrict__ dst,
                               int N, int K, int stride, int off)
{
    int i = blockIdx.x * blockDim.x + threadIdx.x;
    if (i >= N * K) return;
    int n = i / K, k = i % K;
    dst[i] = __float2half_rn(src[(size_t)n * stride + off + k]);
}

__global__ void emb_h_kernel(const float* __restrict__ emb)
{
    int i = blockIdx.x * blockDim.x + threadIdx.x;
    int r = i / Hq, j = i % Hq;
    int t = r / Bq, b = r % Bq;
    g_e_h[i] = __float2half_rn(emb[(size_t)g_tokens[b * Tq + t] * Hq + j]);
}

__global__ void bias_cat_kernel(const float* __restrict__ bua, const float* __restrict__ bhh,
                                const float* __restrict__ ba)
{
    int i = blockIdx.x * blockDim.x + threadIdx.x;  // 4096
    g_bcat[i] = (i < Hq) ? bua[i] : bhh[i - Hq];
    g_bkA[i]  = (i < Hq) ? ba[i] : 0.f;
}

__global__ void copy_h0_kernel(float* __restrict__ dst, const float* __restrict__ src)
{
    int i = blockIdx.x * blockDim.x + threadIdx.x;
    float v = src[i];
    dst[i] = v;
    g_h_h[i] = __float2half_rn(v);
}

__global__ void copy_kernel(float* __restrict__ dst, const float* __restrict__ src)
{
    int i = blockIdx.x * blockDim.x + threadIdx.x;
    dst[i] = src[i];
}

// ---------------- fused attention + GRU ----------------
__global__ void __launch_bounds__(128)
attn_gru_kernel(const float* __restrict__ Va, const float* __restrict__ bva,
                float* __restrict__ att_out,
                const float* __restrict__ hcur, float* __restrict__ hnext, int t)
{
    const int b = blockIdx.x;
    const int tid = threadIdx.x;

    float partial[Sq];
#pragma unroll
    for (int s = 0; s < Sq; s++) partial[s] = 0.f;

    for (int h = tid; h < Hq; h += 128) {
        float qv = g_qgh[b * 4096 + h];
        float va = Va[h];
#pragma unroll
        for (int s = 0; s < Sq; s++) {
            float kw = g_keysA[((size_t)b * Sq + s) * 4096 + h];
            partial[s] += va * tanhf(kw + qv);
        }
    }

    __shared__ float red[4][Sq];
    __shared__ float w[Sq];
    __shared__ float gic_s[3 * Hq];
    int lane = tid & 31, warp = tid >> 5;
#pragma unroll
    for (int s = 0; s < Sq; s++) {
        float v = partial[s];
#pragma unroll
        for (int o = 16; o > 0; o >>= 1) v += __shfl_xor_sync(0xffffffffu, v, o);
        if (lane == 0) red[warp][s] = v;
    }
    __syncthreads();

    if (tid == 0) {
        float scv[Sq], mx = -1e30f;
#pragma unroll
        for (int s = 0; s < Sq; s++) {
            scv[s] = red[0][s] + red[1][s] + red[2][s] + red[3][s] + bva[0];
            mx = fmaxf(mx, scv[s]);
        }
        float sum = 0.f;
#pragma unroll
        for (int s = 0; s < Sq; s++) { scv[s] = expf(scv[s] - mx); sum += scv[s]; }
        float inv = 1.f / sum;
#pragma unroll
        for (int s = 0; s < Sq; s++) w[s] = scv[s] * inv;
    }
    __syncthreads();

    if (tid < Sq) att_out[(size_t)b * (Tq * Sq) + t * Sq + tid] = w[tid];

    const float* kA = g_keysA + (size_t)b * Sq * 4096 + 1024;
    for (int j = tid; j < 3 * Hq; j += 128) {
        float acc = 0.f;
#pragma unroll
        for (int s = 0; s < Sq; s++)
            acc += w[s] * kA[(size_t)s * 4096 + j];
        gic_s[j] = acc;
    }
    __syncthreads();

    const float* gie = g_gie + (size_t)(t * Bq + b) * 3 * Hq;
    const float* gh  = g_qgh + (size_t)b * 4096 + Hq;
    for (int j = tid; j < Hq; j += 128) {
        float r = 1.f / (1.f + expf(-(gie[j] + gic_s[j] + gh[j])));
        float z = 1.f / (1.f + expf(-(gie[Hq + j] + gic_s[Hq + j] + gh[Hq + j])));
        float n = tanhf(gie[2 * Hq + j] + gic_s[2 * Hq + j] + r * gh[2 * Hq + j]);
        float hv = (1.f - z) * n + z * hcur[b * Hq + j];
        hnext[b * Hq + j] = hv;
        __half hh = __float2half_rn(hv);
        g_hall[(size_t)(t * Bq + b) * Hq + j] = hh;
        g_h_h[b * Hq + j] = hh;
    }
}

// ---------------- log_softmax over a row range [r0, r0+gridDim) ----------------
__global__ void __launch_bounds__(256)
logsoftmax_range_kernel(float* __restrict__ out, int r0)
{
    const int r = r0 + blockIdx.x, tid = threadIdx.x;
    const int t = r / Bq, b = r % Bq;
    const float* row = g_logits_all + (size_t)r * Vq;

    float m = -1e30f, s = 0.f;
    for (int v = tid; v < Vq; v += 256) {
        float x = row[v];
        float nm = fmaxf(m, x);
        s = s * expf(m - nm) + expf(x - nm);
        m = nm;
    }
    int lane = tid & 31, warp = tid >> 5;
#pragma unroll
    for (int o = 16; o > 0; o >>= 1) {
        float m2 = __shfl_xor_sync(0xffffffffu, m, o);
        float s2 = __shfl_xor_sync(0xffffffffu, s, o);
        float nm = fmaxf(m, m2);
        s = s * expf(m - nm) + s2 * expf(m2 - nm);
        m = nm;
    }
    __shared__ float sm[8], ss[8];
    __shared__ float lse_sh;
    if (lane == 0) { sm[warp] = m; ss[warp] = s; }
    __syncthreads();
    if (tid == 0) {
        float M = sm[0], S = ss[0];
#pragma unroll
        for (int i = 1; i < 8; i++) {
            float nm = fmaxf(M, sm[i]);
            S = S * expf(M - nm) + ss[i] * expf(sm[i] - nm);
            M = nm;
        }
        lse_sh = M + logf(S);
    }
    __syncthreads();
    float lse = lse_sh;
    float* orow = out + ((size_t)b * Tq + t) * Vq;
    for (int v = tid; v < Vq; v += 256) orow[v] = row[v] - lse;
}

// ---------------- launch ----------------
extern "C" void kernel_launch(void* const* d_in, const int* in_sizes, int n_in,
                              void* d_out, int out_size)
{
    const float* enc_out = (const float*)d_in[0];
    const float* enc_hid = (const float*)d_in[1];
    const int*   target  = (const int*)  d_in[2];
    const float* emb     = (const float*)d_in[3];
    const float* Wa      = (const float*)d_in[4];
    const float* ba      = (const float*)d_in[5];
    const float* Ua      = (const float*)d_in[6];
    const float* bua     = (const float*)d_in[7];
    const float* Va      = (const float*)d_in[8];
    const float* bva     = (const float*)d_in[9];
    const float* W_ih    = (const float*)d_in[10];
    const float* W_hh    = (const float*)d_in[11];
    const float* b_ih    = (const float*)d_in[12];
    const float* b_hh    = (const float*)d_in[13];
    const float* W_out   = (const float*)d_in[14];
    const float* b_out   = (const float*)d_in[15];

    float* out = (float*)d_out;
    const size_t HID_OFF = (size_t)Bq * Tq * Vq;
    const size_t ATT_OFF = HID_OFF + (size_t)Bq * Hq;

    float *keysA, *gie, *h0, *h1, *logitsA, *bcat, *bkA, *qgh;
    __half *enc_h, *e_h, *WkA, *Wqh, *We, *h_h, *hall, *Wout_h;
    cudaGetSymbolAddress((void**)&keysA, g_keysA);
    cudaGetSymbolAddress((void**)&gie, g_gie);
    cudaGetSymbolAddress((void**)&h0, g_h0);
    cudaGetSymbolAddress((void**)&h1, g_h1);
    cudaGetSymbolAddress((void**)&logitsA, g_logits_all);
    cudaGetSymbolAddress((void**)&bcat, g_bcat);
    cudaGetSymbolAddress((void**)&bkA, g_bkA);
    cudaGetSymbolAddress((void**)&qgh, g_qgh);
    cudaGetSymbolAddress((void**)&enc_h, g_enc_h);
    cudaGetSymbolAddress((void**)&e_h, g_e_h);
    cudaGetSymbolAddress((void**)&WkA, g_WkA);
    cudaGetSymbolAddress((void**)&Wqh, g_Wqh);
    cudaGetSymbolAddress((void**)&We, g_We);
    cudaGetSymbolAddress((void**)&h_h, g_h_h);
    cudaGetSymbolAddress((void**)&hall, g_hall);
    cudaGetSymbolAddress((void**)&Wout_h, g_Wout_h);

    cudaFuncSetAttribute((const void*)GEMM_BIG,
                         cudaFuncAttributeMaxDynamicSharedMemorySize, DSM_BIG);
    cudaFuncSetAttribute((const void*)GEMM_SMALL,
                         cudaFuncAttributeMaxDynamicSharedMemorySize, DSM_SMALL);

    static cudaStream_t s_side = 0;
    static cudaEvent_t evFork, evWout, evG0, evS0;
    static bool inited = false;
    if (!inited) {
        cudaStreamCreateWithFlags(&s_side, cudaStreamNonBlocking);
        cudaEventCreateWithFlags(&evFork, cudaEventDisableTiming);
        cudaEventCreateWithFlags(&evWout, cudaEventDisableTiming);
        cudaEventCreateWithFlags(&evG0, cudaEventDisableTiming);
        cudaEventCreateWithFlags(&evS0, cudaEventDisableTiming);
        inited = true;
    }

    // ---- setup (W_out convert hidden under it on side stream) ----
    init_tokens_kernel<<<1, 256>>>(target);
    cudaEventRecord(evFork, 0);
    cudaStreamWaitEvent(s_side, evFork, 0);
    f2h_kernel<<<(Vq * Hq / 4 + 255) / 256, 256, 0, s_side>>>(W_out, Wout_h, Vq * Hq / 4);
    cudaEventRecord(evWout, s_side);

    emb_h_kernel<<<(BT * Hq) / 256, 256>>>(emb);
    slice_h_kernel<<<(3 * Hq * Hq + 255) / 256, 256>>>(W_ih, We, 3 * Hq, Hq, 2 * Hq, 0);
    // gi_e all steps = E @ W_e^T + b_ih  (M=2560, N=3072, K=1024)
    GEMM_BIG<<<dim3(3 * Hq / 128, BT / 128), 256, DSM_BIG>>>(
        e_h, We, b_ih, gie, BT, 3 * Hq, Hq);

    f2h_kernel<<<(Bq * Sq * Hq / 4 + 255) / 256, 256>>>(enc_out, enc_h, Bq * Sq * Hq / 4);
    f2h_kernel<<<(Hq * Hq / 4 + 255) / 256, 256>>>(Wa, WkA, Hq * Hq / 4);
    slice_h_kernel<<<(3 * Hq * Hq + 255) / 256, 256>>>(W_ih, WkA + (size_t)Hq * Hq,
                                                       3 * Hq, Hq, 2 * Hq, Hq);
    bias_cat_kernel<<<16, 256>>>(bua, b_hh, ba);
    // keysA = enc @ [Wa;Wc]^T + [ba|0]  (M=2560, N=4096, K=1024)
    GEMM_BIG<<<dim3(4096 / 128, (Bq * Sq) / 128), 256, DSM_BIG>>>(
        enc_h, WkA, bkA, keysA, Bq * Sq, 4096, Hq);

    copy_h0_kernel<<<(Bq * Hq) / 256, 256>>>(h0, enc_hid);
    f2h_kernel<<<(Hq * Hq / 4 + 255) / 256, 256>>>(Ua, Wqh, Hq * Hq / 4);
    f2h_kernel<<<(3 * Hq * Hq / 4 + 255) / 256, 256>>>(W_hh, Wqh + (size_t)Hq * Hq,
                                                       3 * Hq * Hq / 4);

    // ---- serial recurrence (NOTHING overlaps this) ----
    float* hcur = h0;
    float* hnext = h1;
    for (int t = 0; t < Tq; t++) {
        GEMM_SMALL<<<dim3(4096 / 64, Bq / 64), 128, DSM_SMALL>>>(
            h_h, Wqh, bcat, qgh, Bq, 4096, Hq);
        attn_gru_kernel<<<Bq, 128>>>(Va, bva, out + ATT_OFF, hcur, hnext, t);
        float* tmp = hcur; hcur = hnext; hnext = tmp;
    }

    // h_last
    copy_kernel<<<(Bq * Hq) / 256, 256>>>(out + HID_OFF, hcur);

    // ---- logits in two halves; softmax(half0) overlaps GEMM(half1) ----
    cudaStreamWaitEvent(0, evWout, 0);  // ensure W_out convert finished
    GEMM_BIG<<<dim3(Vq / 128, (5 * Bq) / 128), 256, DSM_BIG>>>(
        hall, Wout_h, b_out, logitsA, 5 * Bq, Vq, Hq);
    cudaEventRecord(evG0, 0);

    GEMM_BIG<<<dim3(Vq / 128, (5 * Bq) / 128), 256, DSM_BIG>>>(
        hall + (size_t)5 * Bq * Hq, Wout_h, b_out,
        logitsA + (size_t)5 * Bq * Vq, 5 * Bq, Vq, Hq);

    // softmax half-0 on side stream, concurrent with GEMM half-1
    cudaStreamWaitEvent(s_side, evG0, 0);
    logsoftmax_range_kernel<<<5 * Bq, 256, 0, s_side>>>(out, 0);
    cudaEventRecord(evS0, s_side);

    // softmax half-1 on main
    logsoftmax_range_kernel<<<5 * Bq, 256>>>(out, 5 * Bq);

    // join
    cudaStreamWaitEvent(0, evS0, 0);
}

// round 17
// speedup vs baseline: 1.6363x; 1.0961x over previous
#include <cuda_runtime.h>
#include <cuda_fp16.h>
#include <math.h>
#include <stdint.h>

#define Bq 256
#define Sq 10
#define Hq 1024
#define Vq 32000
#define Tq 10
#define BT (Bq * Tq)

// ---------------- device scratch (no allocation) ----------------
__device__ __align__(16) float g_keysA[(size_t)Bq * Sq * 4096];  // [ keysW(1024) | keysC(3072) ]
__device__ int   g_tokens[Bq * Tq];
__device__ __align__(16) float g_qgh[Bq * 4096];
__device__ __align__(16) float g_gie[(size_t)BT * 3 * Hq];
__device__ __align__(16) float g_h0[Bq * Hq];
__device__ __align__(16) float g_h1[Bq * Hq];
__device__ __align__(16) __half g_logits_h[(size_t)BT * Vq];
__device__ __align__(16) float g_bcat[4096];
__device__ __align__(16) float g_bkA[4096];

__device__ __align__(16) __half g_enc_h[(size_t)Bq * Sq * Hq];
__device__ __align__(16) __half g_e_h[(size_t)BT * Hq];
__device__ __align__(16) __half g_WkA[(size_t)4096 * Hq];   // [Wa; Wc]
__device__ __align__(16) __half g_Wqh[(size_t)4096 * Hq];   // [Ua; Whh]
__device__ __align__(16) __half g_We[(size_t)3 * Hq * Hq];
__device__ __align__(16) __half g_h_h[Bq * Hq];
__device__ __align__(16) __half g_hall[(size_t)BT * Hq];
__device__ __align__(16) __half g_Wout_h[(size_t)Vq * Hq];

// ---------------- fp16 HMMA GEMM: 3-stage cp.async ring; templated output ----------------
template <int BM, int BN, int BK, int WM, int WN, int MINB, typename TO>
__global__ void __launch_bounds__((BM / WM) * (BN / WN) * 32, MINB)
gemm_fp16_bias(const __half* __restrict__ A, const __half* __restrict__ B,
               const float* __restrict__ bias, TO* __restrict__ C,
               int M, int N, int K)
{
    constexpr int WARPS_M = BM / WM;
    constexpr int WARPS_N = BN / WN;
    constexpr int THREADS = WARPS_M * WARPS_N * 32;
    constexpr int PAD = 8;
    constexpr int LDS_ = BK + PAD;
    constexpr int MI = WM / 16;
    constexpr int NI = WN / 8;

    extern __shared__ char smem_raw[];
    __half* As = (__half*)smem_raw;
    __half* Bs = (__half*)(smem_raw + 3 * BM * LDS_ * 2);

    const int tid = threadIdx.x;
    const int wid = tid / 32, lane = tid % 32;
    const int wm = (wid / WARPS_N) * WM;
    const int wn = (wid % WARPS_N) * WN;
    const int bm = blockIdx.y * BM;
    const int bn = blockIdx.x * BN;

    constexpr int A_CH = BM * BK / 8;
    constexpr int B_CH = BN * BK / 8;
    constexpr int CPR = BK / 8;

    const int NK = K / BK;

    auto load_stage = [&](int stage) {
        __half* Asd = As + (stage % 3) * BM * LDS_;
        __half* Bsd = Bs + (stage % 3) * BN * LDS_;
        const int k0 = stage * BK;
#pragma unroll
        for (int c = tid; c < A_CH; c += THREADS) {
            int r = c / CPR, cc = (c % CPR) * 8;
            uint32_t sdst = (uint32_t)__cvta_generic_to_shared(&Asd[r * LDS_ + cc]);
            const __half* src = &A[(size_t)(bm + r) * K + k0 + cc];
            asm volatile("cp.async.cg.shared.global [%0], [%1], 16;" :: "r"(sdst), "l"(src));
        }
#pragma unroll
        for (int c = tid; c < B_CH; c += THREADS) {
            int r = c / CPR, cc = (c % CPR) * 8;
            uint32_t sdst = (uint32_t)__cvta_generic_to_shared(&Bsd[r * LDS_ + cc]);
            const __half* src = &B[(size_t)(bn + r) * K + k0 + cc];
            asm volatile("cp.async.cg.shared.global [%0], [%1], 16;" :: "r"(sdst), "l"(src));
        }
        asm volatile("cp.async.commit_group;");
    };

    float acc[MI][NI][4];
#pragma unroll
    for (int i = 0; i < MI; i++)
#pragma unroll
        for (int j = 0; j < NI; j++)
#pragma unroll
            for (int k = 0; k < 4; k++) acc[i][j][k] = 0.f;

    load_stage(0);
    if (NK > 1) load_stage(1);

    const int a_row = lane % 16;
    const int a_col = (lane / 16) * 8;
    const int b_t   = lane & 15;
    const int b_row = b_t % 8;
    const int b_col = (b_t / 8) * 8;

    for (int kt = 0; kt < NK; kt++) {
        if (kt + 1 < NK) {
            asm volatile("cp.async.wait_group 1;");
        } else {
            asm volatile("cp.async.wait_group 0;");
        }
        __syncthreads();

        if (kt + 2 < NK) load_stage(kt + 2);

        __half* Asb = As + (kt % 3) * BM * LDS_;
        __half* Bsb = Bs + (kt % 3) * BN * LDS_;

#pragma unroll
        for (int kk = 0; kk < BK; kk += 16) {
            uint32_t af[MI][4];
#pragma unroll
            for (int mi = 0; mi < MI; mi++) {
                uint32_t addr = (uint32_t)__cvta_generic_to_shared(
                    &Asb[(wm + mi * 16 + a_row) * LDS_ + kk + a_col]);
                asm volatile("ldmatrix.sync.aligned.m8n8.x4.shared.b16 {%0,%1,%2,%3}, [%4];"
                             : "=r"(af[mi][0]), "=r"(af[mi][1]), "=r"(af[mi][2]), "=r"(af[mi][3])
                             : "r"(addr));
            }
            uint32_t bf[NI][2];
#pragma unroll
            for (int ni = 0; ni < NI; ni++) {
                uint32_t addr = (uint32_t)__cvta_generic_to_shared(
                    &Bsb[(wn + ni * 8 + b_row) * LDS_ + kk + b_col]);
                asm volatile("ldmatrix.sync.aligned.m8n8.x2.shared.b16 {%0,%1}, [%2];"
                             : "=r"(bf[ni][0]), "=r"(bf[ni][1])
                             : "r"(addr));
            }
#pragma unroll
            for (int mi = 0; mi < MI; mi++) {
#pragma unroll
                for (int ni = 0; ni < NI; ni++) {
                    asm volatile(
                        "mma.sync.aligned.m16n8k16.row.col.f32.f16.f16.f32 "
                        "{%0,%1,%2,%3}, {%4,%5,%6,%7}, {%8,%9}, {%0,%1,%2,%3};"
                        : "+f"(acc[mi][ni][0]), "+f"(acc[mi][ni][1]),
                          "+f"(acc[mi][ni][2]), "+f"(acc[mi][ni][3])
                        : "r"(af[mi][0]), "r"(af[mi][1]), "r"(af[mi][2]), "r"(af[mi][3]),
                          "r"(bf[ni][0]), "r"(bf[ni][1]));
                }
            }
        }
    }

#pragma unroll
    for (int mi = 0; mi < MI; mi++) {
        int row0 = bm + wm + mi * 16 + lane / 4;
#pragma unroll
        for (int ni = 0; ni < NI; ni++) {
            int col = bn + wn + ni * 8 + 2 * (lane % 4);
            float2 bv = *(const float2*)&bias[col];
            float v00 = acc[mi][ni][0] + bv.x, v01 = acc[mi][ni][1] + bv.y;
            float v10 = acc[mi][ni][2] + bv.x, v11 = acc[mi][ni][3] + bv.y;
            if constexpr (sizeof(TO) == 4) {
                *(float2*)&C[(size_t)row0 * N + col] = make_float2(v00, v01);
                *(float2*)&C[(size_t)(row0 + 8) * N + col] = make_float2(v10, v11);
            } else {
                __half2 h0 = __floats2half2_rn(v00, v01);
                __half2 h1 = __floats2half2_rn(v10, v11);
                *(__half2*)&C[(size_t)row0 * N + col] = h0;
                *(__half2*)&C[(size_t)(row0 + 8) * N + col] = h1;
            }
        }
    }
}

// smem sizes (3 stages)
#define DSM_BIG   (3 * (128 + 128) * (64 + 8) * 2)   // 110592 (2 CTA/SM)
#define DSM_SMALL (3 * (64 + 64) * (64 + 8) * 2)     // 55296

#define GEMM_BIG    gemm_fp16_bias<128, 128, 64, 64, 32, 2, float>
#define GEMM_BIG_H  gemm_fp16_bias<128, 128, 64, 64, 32, 2, __half>
#define GEMM_SMALL  gemm_fp16_bias<64, 64, 64, 32, 32, 4, float>

// ---------------- setup / conversion kernels ----------------
__global__ void init_tokens_kernel(const int* __restrict__ target)
{
    int b = threadIdx.x;
    g_tokens[b * Tq + 0] = 0;  // SOS
    for (int t = 1; t < Tq; t++) g_tokens[b * Tq + t] = target[b * Tq + t - 1];
}

__global__ void f2h_kernel(const float* __restrict__ src, __half* __restrict__ dst, int n4)
{
    int i = blockIdx.x * blockDim.x + threadIdx.x;
    if (i >= n4) return;
    float4 v = ((const float4*)src)[i];
    __half2 lo = __floats2half2_rn(v.x, v.y);
    __half2 hi = __floats2half2_rn(v.z, v.w);
    uint2 o;
    o.x = *(uint32_t*)&lo;
    o.y = *(uint32_t*)&hi;
    ((uint2*)dst)[i] = o;
}

__global__ void slice_h_kernel(const float* __restrict__ src, __half* __restrict__ dst,
                               int N, int K, int stride, int off)
{
    int i = blockIdx.x * blockDim.x + threadIdx.x;
    if (i >= N * K) return;
    int n = i / K, k = i % K;
    dst[i] = __float2half_rn(src[(size_t)n * stride + off + k]);
}

__global__ void emb_h_kernel(const float* __restrict__ emb)
{
    int i = blockIdx.x * blockDim.x + threadIdx.x;
    int r = i / Hq, j = i % Hq;
    int t = r / Bq, b = r % Bq;
    g_e_h[i] = __float2half_rn(emb[(size_t)g_tokens[b * Tq + t] * Hq + j]);
}

__global__ void bias_cat_kernel(const float* __restrict__ bua, const float* __restrict__ bhh,
                                const float* __restrict__ ba)
{
    int i = blockIdx.x * blockDim.x + threadIdx.x;  // 4096
    g_bcat[i] = (i < Hq) ? bua[i] : bhh[i - Hq];
    g_bkA[i]  = (i < Hq) ? ba[i] : 0.f;
}

__global__ void copy_h0_kernel(float* __restrict__ dst, const float* __restrict__ src)
{
    int i = blockIdx.x * blockDim.x + threadIdx.x;
    float v = src[i];
    dst[i] = v;
    g_h_h[i] = __float2half_rn(v);
}

__global__ void copy_kernel(float* __restrict__ dst, const float* __restrict__ src)
{
    int i = blockIdx.x * blockDim.x + threadIdx.x;
    dst[i] = src[i];
}

// ---------------- fused attention + GRU ----------------
__global__ void __launch_bounds__(128)
attn_gru_kernel(const float* __restrict__ Va, const float* __restrict__ bva,
                float* __restrict__ att_out,
                const float* __restrict__ hcur, float* __restrict__ hnext, int t)
{
    const int b = blockIdx.x;
    const int tid = threadIdx.x;

    float partial[Sq];
#pragma unroll
    for (int s = 0; s < Sq; s++) partial[s] = 0.f;

    for (int h = tid; h < Hq; h += 128) {
        float qv = g_qgh[b * 4096 + h];
        float va = Va[h];
#pragma unroll
        for (int s = 0; s < Sq; s++) {
            float kw = g_keysA[((size_t)b * Sq + s) * 4096 + h];
            partial[s] += va * tanhf(kw + qv);
        }
    }

    __shared__ float red[4][Sq];
    __shared__ float w[Sq];
    __shared__ float gic_s[3 * Hq];
    int lane = tid & 31, warp = tid >> 5;
#pragma unroll
    for (int s = 0; s < Sq; s++) {
        float v = partial[s];
#pragma unroll
        for (int o = 16; o > 0; o >>= 1) v += __shfl_xor_sync(0xffffffffu, v, o);
        if (lane == 0) red[warp][s] = v;
    }
    __syncthreads();

    if (tid == 0) {
        float scv[Sq], mx = -1e30f;
#pragma unroll
        for (int s = 0; s < Sq; s++) {
            scv[s] = red[0][s] + red[1][s] + red[2][s] + red[3][s] + bva[0];
            mx = fmaxf(mx, scv[s]);
        }
        float sum = 0.f;
#pragma unroll
        for (int s = 0; s < Sq; s++) { scv[s] = expf(scv[s] - mx); sum += scv[s]; }
        float inv = 1.f / sum;
#pragma unroll
        for (int s = 0; s < Sq; s++) w[s] = scv[s] * inv;
    }
    __syncthreads();

    if (tid < Sq) att_out[(size_t)b * (Tq * Sq) + t * Sq + tid] = w[tid];

    const float* kA = g_keysA + (size_t)b * Sq * 4096 + 1024;
    for (int j = tid; j < 3 * Hq; j += 128) {
        float acc = 0.f;
#pragma unroll
        for (int s = 0; s < Sq; s++)
            acc += w[s] * kA[(size_t)s * 4096 + j];
        gic_s[j] = acc;
    }
    __syncthreads();

    const float* gie = g_gie + (size_t)(t * Bq + b) * 3 * Hq;
    const float* gh  = g_qgh + (size_t)b * 4096 + Hq;
    for (int j = tid; j < Hq; j += 128) {
        float r = 1.f / (1.f + expf(-(gie[j] + gic_s[j] + gh[j])));
        float z = 1.f / (1.f + expf(-(gie[Hq + j] + gic_s[Hq + j] + gh[Hq + j])));
        float n = tanhf(gie[2 * Hq + j] + gic_s[2 * Hq + j] + r * gh[2 * Hq + j]);
        float hv = (1.f - z) * n + z * hcur[b * Hq + j];
        hnext[b * Hq + j] = hv;
        __half hh = __float2half_rn(hv);
        g_hall[(size_t)(t * Bq + b) * Hq + j] = hh;
        g_h_h[b * Hq + j] = hh;
    }
}

// ---------------- batched log_softmax over fp16 logits (row r = t*Bq + b) ----------------
__global__ void __launch_bounds__(256)
logsoftmax_all_kernel(float* __restrict__ out)
{
    const int r = blockIdx.x, tid = threadIdx.x;
    const int t = r / Bq, b = r % Bq;
    const __half2* row2 = (const __half2*)(g_logits_h + (size_t)r * Vq);

    float m = -1e30f, s = 0.f;
    for (int v = tid; v < Vq / 2; v += 256) {
        float2 x2 = __half22float2(row2[v]);
        float nm = fmaxf(m, fmaxf(x2.x, x2.y));
        s = s * expf(m - nm) + expf(x2.x - nm) + expf(x2.y - nm);
        m = nm;
    }
    int lane = tid & 31, warp = tid >> 5;
#pragma unroll
    for (int o = 16; o > 0; o >>= 1) {
        float m2 = __shfl_xor_sync(0xffffffffu, m, o);
        float s2 = __shfl_xor_sync(0xffffffffu, s, o);
        float nm = fmaxf(m, m2);
        s = s * expf(m - nm) + s2 * expf(m2 - nm);
        m = nm;
    }
    __shared__ float sm[8], ss[8];
    __shared__ float lse_sh;
    if (lane == 0) { sm[warp] = m; ss[warp] = s; }
    __syncthreads();
    if (tid == 0) {
        float M = sm[0], S = ss[0];
#pragma unroll
        for (int i = 1; i < 8; i++) {
            float nm = fmaxf(M, sm[i]);
            S = S * expf(M - nm) + ss[i] * expf(sm[i] - nm);
            M = nm;
        }
        lse_sh = M + logf(S);
    }
    __syncthreads();
    float lse = lse_sh;
    float2* orow2 = (float2*)(out + ((size_t)b * Tq + t) * Vq);
    for (int v = tid; v < Vq / 2; v += 256) {
        float2 x2 = __half22float2(row2[v]);
        orow2[v] = make_float2(x2.x - lse, x2.y - lse);
    }
}

// ---------------- launch ----------------
extern "C" void kernel_launch(void* const* d_in, const int* in_sizes, int n_in,
                              void* d_out, int out_size)
{
    const float* enc_out = (const float*)d_in[0];
    const float* enc_hid = (const float*)d_in[1];
    const int*   target  = (const int*)  d_in[2];
    const float* emb     = (const float*)d_in[3];
    const float* Wa      = (const float*)d_in[4];
    const float* ba      = (const float*)d_in[5];
    const float* Ua      = (const float*)d_in[6];
    const float* bua     = (const float*)d_in[7];
    const float* Va      = (const float*)d_in[8];
    const float* bva     = (const float*)d_in[9];
    const float* W_ih    = (const float*)d_in[10];
    const float* W_hh    = (const float*)d_in[11];
    const float* b_ih    = (const float*)d_in[12];
    const float* b_hh    = (const float*)d_in[13];
    const float* W_out   = (const float*)d_in[14];
    const float* b_out   = (const float*)d_in[15];

    float* out = (float*)d_out;
    const size_t HID_OFF = (size_t)Bq * Tq * Vq;
    const size_t ATT_OFF = HID_OFF + (size_t)Bq * Hq;

    float *keysA, *gie, *h0, *h1, *bcat, *bkA, *qgh;
    __half *enc_h, *e_h, *WkA, *Wqh, *We, *h_h, *hall, *Wout_h, *logitsH;
    cudaGetSymbolAddress((void**)&keysA, g_keysA);
    cudaGetSymbolAddress((void**)&gie, g_gie);
    cudaGetSymbolAddress((void**)&h0, g_h0);
    cudaGetSymbolAddress((void**)&h1, g_h1);
    cudaGetSymbolAddress((void**)&logitsH, g_logits_h);
    cudaGetSymbolAddress((void**)&bcat, g_bcat);
    cudaGetSymbolAddress((void**)&bkA, g_bkA);
    cudaGetSymbolAddress((void**)&qgh, g_qgh);
    cudaGetSymbolAddress((void**)&enc_h, g_enc_h);
    cudaGetSymbolAddress((void**)&e_h, g_e_h);
    cudaGetSymbolAddress((void**)&WkA, g_WkA);
    cudaGetSymbolAddress((void**)&Wqh, g_Wqh);
    cudaGetSymbolAddress((void**)&We, g_We);
    cudaGetSymbolAddress((void**)&h_h, g_h_h);
    cudaGetSymbolAddress((void**)&hall, g_hall);
    cudaGetSymbolAddress((void**)&Wout_h, g_Wout_h);

    cudaFuncSetAttribute((const void*)GEMM_BIG,
                         cudaFuncAttributeMaxDynamicSharedMemorySize, DSM_BIG);
    cudaFuncSetAttribute((const void*)GEMM_BIG_H,
                         cudaFuncAttributeMaxDynamicSharedMemorySize, DSM_BIG);
    cudaFuncSetAttribute((const void*)GEMM_SMALL,
                         cudaFuncAttributeMaxDynamicSharedMemorySize, DSM_SMALL);

    static cudaStream_t s_side = 0;
    static cudaEvent_t evFork, evWout;
    static bool inited = false;
    if (!inited) {
        cudaStreamCreateWithFlags(&s_side, cudaStreamNonBlocking);
        cudaEventCreateWithFlags(&evFork, cudaEventDisableTiming);
        cudaEventCreateWithFlags(&evWout, cudaEventDisableTiming);
        inited = true;
    }

    // ---- setup (W_out convert hidden under it on side stream) ----
    init_tokens_kernel<<<1, 256>>>(target);
    cudaEventRecord(evFork, 0);
    cudaStreamWaitEvent(s_side, evFork, 0);
    f2h_kernel<<<(Vq * Hq / 4 + 255) / 256, 256, 0, s_side>>>(W_out, Wout_h, Vq * Hq / 4);
    cudaEventRecord(evWout, s_side);

    emb_h_kernel<<<(BT * Hq) / 256, 256>>>(emb);
    slice_h_kernel<<<(3 * Hq * Hq + 255) / 256, 256>>>(W_ih, We, 3 * Hq, Hq, 2 * Hq, 0);
    // gi_e all steps = E @ W_e^T + b_ih  (M=2560, N=3072, K=1024)
    GEMM_BIG<<<dim3(3 * Hq / 128, BT / 128), 256, DSM_BIG>>>(
        e_h, We, b_ih, gie, BT, 3 * Hq, Hq);

    f2h_kernel<<<(Bq * Sq * Hq / 4 + 255) / 256, 256>>>(enc_out, enc_h, Bq * Sq * Hq / 4);
    f2h_kernel<<<(Hq * Hq / 4 + 255) / 256, 256>>>(Wa, WkA, Hq * Hq / 4);
    slice_h_kernel<<<(3 * Hq * Hq + 255) / 256, 256>>>(W_ih, WkA + (size_t)Hq * Hq,
                                                       3 * Hq, Hq, 2 * Hq, Hq);
    bias_cat_kernel<<<16, 256>>>(bua, b_hh, ba);
    // keysA = enc @ [Wa;Wc]^T + [ba|0]  (M=2560, N=4096, K=1024)
    GEMM_BIG<<<dim3(4096 / 128, (Bq * Sq) / 128), 256, DSM_BIG>>>(
        enc_h, WkA, bkA, keysA, Bq * Sq, 4096, Hq);

    copy_h0_kernel<<<(Bq * Hq) / 256, 256>>>(h0, enc_hid);
    f2h_kernel<<<(Hq * Hq / 4 + 255) / 256, 256>>>(Ua, Wqh, Hq * Hq / 4);
    f2h_kernel<<<(3 * Hq * Hq / 4 + 255) / 256, 256>>>(W_hh, Wqh + (size_t)Hq * Hq,
                                                       3 * Hq * Hq / 4);

    // ---- serial recurrence (nothing overlaps this) ----
    float* hcur = h0;
    float* hnext = h1;
    for (int t = 0; t < Tq; t++) {
        GEMM_SMALL<<<dim3(4096 / 64, Bq / 64), 128, DSM_SMALL>>>(
            h_h, Wqh, bcat, qgh, Bq, 4096, Hq);
        attn_gru_kernel<<<Bq, 128>>>(Va, bva, out + ATT_OFF, hcur, hnext, t);
        float* tmp = hcur; hcur = hnext; hnext = tmp;
    }

    // h_last
    copy_kernel<<<(Bq * Hq) / 256, 256>>>(out + HID_OFF, hcur);

    // ---- batched logits (fp16 out) + batched log_softmax ----
    cudaStreamWaitEvent(0, evWout, 0);  // ensure W_out convert finished
    GEMM_BIG_H<<<dim3(Vq / 128, BT / 128), 256, DSM_BIG>>>(
        hall, Wout_h, b_out, logitsH, BT, Vq, Hq);
    logsoftmax_all_kernel<<<BT, 256>>>(out);
}